// round 4
// baseline (speedup 1.0000x reference)
#include <cuda_runtime.h>
#include <math.h>

#define NB   64      // batch
#define CL   51      // caption length L
#define NT   50      // time steps T = L-1
#define ED   512     // embed dim E
#define HD   512     // hidden H
#define VD   30000   // vocab V
#define ENCD 2048    // encoder dim
#define GD   2048    // 4*H gates

// ---------------- device scratch (static, allocation-free) ----------------
__device__ int   g_sort[NB];
__device__ int   g_dlen[NB];
__device__ float g_h[NB * HD];
__device__ float g_c[NB * HD];
__device__ float g_XW[(size_t)NT * NB * GD];      // x@w_ih^T + b_ih, all steps (26 MB)
__device__ float g_parts[4][NB * GD];             // K-split partials of h@w_hh^T
__device__ float g_H[(size_t)NT * NB * HD];       // all hidden states (t,b,k)

// ---------------- common GEMM tile helpers (64x64 tile, BK=32, 4x4 micro) ----------------
__device__ __forceinline__ void stash_tile(float (*S)[65], int lr, int ls, float4 v0, float4 v1) {
    S[ls*4+0][lr] = v0.x; S[ls*4+1][lr] = v0.y; S[ls*4+2][lr] = v0.z; S[ls*4+3][lr] = v0.w;
    S[16+ls*4+0][lr] = v1.x; S[16+ls*4+1][lr] = v1.y; S[16+ls*4+2][lr] = v1.z; S[16+ls*4+3][lr] = v1.w;
}

__device__ __forceinline__ void mm_inner(float (*As)[65], float (*Bs)[65],
                                         float acc[4][4], int tx, int ty) {
#pragma unroll
    for (int kk = 0; kk < 32; kk++) {
        float a0 = As[kk][ty*4+0], a1 = As[kk][ty*4+1];
        float a2 = As[kk][ty*4+2], a3 = As[kk][ty*4+3];
        float b0 = Bs[kk][tx*4+0], b1 = Bs[kk][tx*4+1];
        float b2 = Bs[kk][tx*4+2], b3 = Bs[kk][tx*4+3];
        acc[0][0] += a0*b0; acc[0][1] += a0*b1; acc[0][2] += a0*b2; acc[0][3] += a0*b3;
        acc[1][0] += a1*b0; acc[1][1] += a1*b1; acc[1][2] += a1*b2; acc[1][3] += a1*b3;
        acc[2][0] += a2*b0; acc[2][1] += a2*b1; acc[2][2] += a2*b2; acc[2][3] += a2*b3;
        acc[3][0] += a3*b0; acc[3][1] += a3*b1; acc[3][2] += a3*b2; acc[3][3] += a3*b3;
    }
}

// ---------------- sort + extras ----------------
__global__ void k_sort(const int* __restrict__ lens, const int* __restrict__ caps,
                       float* __restrict__ out_extra, int extras) {
    __shared__ int slen[NB];
    __shared__ int sidx[NB];
    int t = threadIdx.x;
    if (t < NB) slen[t] = lens[t];
    __syncthreads();
    if (t < NB) {
        int Li = slen[t];
        int r = 0;
        for (int j = 0; j < NB; j++) {
            int Lj = slen[j];
            if (Lj > Li || (Lj == Li && j < t)) r++;   // stable descending
        }
        sidx[r] = t;
    }
    __syncthreads();
    if (t < NB) { g_sort[t] = sidx[t]; g_dlen[t] = slen[sidx[t]] - 1; }
    __syncthreads();
    if (extras) {
        for (int i = t; i < NB * CL; i += blockDim.x) {
            int b = i / CL, j = i % CL;
            out_extra[i] = (float)caps[sidx[b] * CL + j];
        }
        if (t < NB) out_extra[NB*CL + t]      = (float)(slen[sidx[t]] - 1);
        if (t < NB) out_extra[NB*CL + NB + t] = (float)sidx[t];
    }
}

// ---------------- init: h0 = enc_sorted @ w_init_h^T + b ; c0 likewise (blockIdx.z) ----------------
__global__ void k_init(const float* __restrict__ enc,
                       const float* __restrict__ wh, const float* __restrict__ bh,
                       const float* __restrict__ wc, const float* __restrict__ bc) {
    __shared__ float As[32][65], Bs[32][65];
    __shared__ int arow[64];
    const float* Wsel = blockIdx.z ? wc : wh;
    const float* bsel = blockIdx.z ? bc : bh;
    float* Csel = blockIdx.z ? g_c : g_h;
    int tid = threadIdx.x;
    if (tid < 64) arow[tid] = g_sort[tid];
    __syncthreads();
    int n0 = blockIdx.x * 64;
    int tx = tid & 15, ty = tid >> 4;
    int lr = tid >> 2, ls = tid & 3;
    float acc[4][4] = {};
    for (int k0 = 0; k0 < ENCD; k0 += 32) {
        const float4* ap = (const float4*)(enc + (size_t)arow[lr] * ENCD + k0);
        stash_tile(As, lr, ls, ap[ls], ap[ls + 4]);
        const float4* bp = (const float4*)(Wsel + (size_t)(n0 + lr) * ENCD + k0);
        stash_tile(Bs, lr, ls, bp[ls], bp[ls + 4]);
        __syncthreads();
        mm_inner(As, Bs, acc, tx, ty);
        __syncthreads();
    }
#pragma unroll
    for (int i = 0; i < 4; i++) {
        int m = ty*4 + i;
#pragma unroll
        for (int j = 0; j < 4; j++) {
            int n = n0 + tx*4 + j;
            Csel[m * HD + n] = acc[i][j] + bsel[n];
        }
    }
}

// ---------------- XW: all-steps input gates = emb_gather @ w_ih^T + b_ih ----------------
__global__ void k_xw(const float* __restrict__ emb, const int* __restrict__ caps,
                     const float* __restrict__ wih, const float* __restrict__ bih) {
    __shared__ float As[32][65], Bs[32][65];
    __shared__ int arow[64];
    int tid = threadIdx.x;
    int t = blockIdx.y;
    if (tid < 64) arow[tid] = caps[g_sort[tid] * CL + t];
    __syncthreads();
    int n0 = blockIdx.x * 64;
    int tx = tid & 15, ty = tid >> 4;
    int lr = tid >> 2, ls = tid & 3;
    float acc[4][4] = {};
    for (int k0 = 0; k0 < ED; k0 += 32) {
        const float4* ap = (const float4*)(emb + (size_t)arow[lr] * ED + k0);
        stash_tile(As, lr, ls, ap[ls], ap[ls + 4]);
        const float4* bp = (const float4*)(wih + (size_t)(n0 + lr) * ED + k0);
        stash_tile(Bs, lr, ls, bp[ls], bp[ls + 4]);
        __syncthreads();
        mm_inner(As, Bs, acc, tx, ty);
        __syncthreads();
    }
    float* outp = g_XW + ((size_t)t * NB) * GD;
#pragma unroll
    for (int i = 0; i < 4; i++) {
        int m = ty*4 + i;
#pragma unroll
        for (int j = 0; j < 4; j++) {
            int n = n0 + tx*4 + j;
            outp[(size_t)m * GD + n] = acc[i][j] + bih[n];
        }
    }
}

// ---------------- per-step: partial h @ w_hh^T (K split by 4 for parallelism) ----------------
__global__ void k_hh(const float* __restrict__ whh) {
    __shared__ float As[32][65], Bs[32][65];
    int tid = threadIdx.x;
    int n0 = blockIdx.x * 64;
    int kbase = blockIdx.y * 128;
    int tx = tid & 15, ty = tid >> 4;
    int lr = tid >> 2, ls = tid & 3;
    float acc[4][4] = {};
    for (int kc = 0; kc < 4; kc++) {
        int k0 = kbase + kc * 32;
        const float4* ap = (const float4*)(g_h + (size_t)lr * HD + k0);
        stash_tile(As, lr, ls, ap[ls], ap[ls + 4]);
        const float4* bp = (const float4*)(whh + (size_t)(n0 + lr) * HD + k0);
        stash_tile(Bs, lr, ls, bp[ls], bp[ls + 4]);
        __syncthreads();
        mm_inner(As, Bs, acc, tx, ty);
        __syncthreads();
    }
    float* outp = g_parts[blockIdx.y];
#pragma unroll
    for (int i = 0; i < 4; i++) {
        int m = ty*4 + i;
#pragma unroll
        for (int j = 0; j < 4; j++) {
            int n = n0 + tx*4 + j;
            outp[m * GD + n] = acc[i][j];
        }
    }
}

// ---------------- per-step: reduce partials + LSTM pointwise ----------------
__global__ void k_point(const float* __restrict__ bhh, int t) {
    int idx = blockIdx.x * blockDim.x + threadIdx.x;   // 128*256 = 32768 = NB*HD
    int b = idx >> 9, j = idx & 511;
    const float* xw = g_XW + ((size_t)t * NB + b) * GD;
    float gi = xw[j]          + bhh[j];
    float gf = xw[512 + j]    + bhh[512 + j];
    float gg = xw[1024 + j]   + bhh[1024 + j];
    float go = xw[1536 + j]   + bhh[1536 + j];
#pragma unroll
    for (int p = 0; p < 4; p++) {
        const float* pp = g_parts[p] + b * GD;
        gi += pp[j]; gf += pp[512 + j]; gg += pp[1024 + j]; go += pp[1536 + j];
    }
    float c = g_c[b * HD + j];
    float si = 1.f / (1.f + expf(-gi));
    float sf = 1.f / (1.f + expf(-gf));
    float so = 1.f / (1.f + expf(-go));
    c = sf * c + si * tanhf(gg);
    float h = so * tanhf(c);
    g_c[b * HD + j] = c;
    g_h[b * HD + j] = h;
    g_H[((size_t)t * NB + b) * HD + j] = h;
}

// ---------------- big FC: preds = H_all @ w_fc^T + b_fc, masked ----------------
__global__ void k_fc(const float* __restrict__ wfc, const float* __restrict__ bfc,
                     float* __restrict__ out) {
    __shared__ float As[32][65], Bs[32][65];
    int tid = threadIdx.x;
    int n0 = blockIdx.x * 64;
    int t = blockIdx.y;
    int tx = tid & 15, ty = tid >> 4;
    int lr = tid >> 2, ls = tid & 3;
    int w = tid >> 5;
    // warps cover 8 consecutive batch rows; lengths sorted desc -> prefix active
    bool wact = (g_dlen[w * 8] > t);
    float acc[4][4] = {};
    const float* Abase = g_H + (size_t)t * NB * HD;
    for (int k0 = 0; k0 < HD; k0 += 32) {
        const float4* ap = (const float4*)(Abase + (size_t)lr * HD + k0);
        stash_tile(As, lr, ls, ap[ls], ap[ls + 4]);
        int nr = n0 + lr;
        float4 b0 = make_float4(0.f, 0.f, 0.f, 0.f), b1 = b0;
        if (nr < VD) {
            const float4* bp = (const float4*)(wfc + (size_t)nr * HD + k0);
            b0 = bp[ls]; b1 = bp[ls + 4];
        }
        stash_tile(Bs, lr, ls, b0, b1);
        __syncthreads();
        if (wact) mm_inner(As, Bs, acc, tx, ty);
        __syncthreads();
    }
#pragma unroll
    for (int i = 0; i < 4; i++) {
        int m = ty*4 + i;
        bool act = (g_dlen[m] > t);
#pragma unroll
        for (int j = 0; j < 4; j++) {
            int n = n0 + tx*4 + j;
            if (n < VD) {
                size_t o = (size_t)m * ((size_t)NT * VD) + (size_t)t * VD + n;
                out[o] = act ? (acc[i][j] + bfc[n]) : 0.0f;
            }
        }
    }
}

// ---------------- launch ----------------
extern "C" void kernel_launch(void* const* d_in, const int* in_sizes, int n_in,
                              void* d_out, int out_size) {
    const float* enc      = (const float*)d_in[0];
    const int*   caps     = (const int*)  d_in[1];
    const int*   clen     = (const int*)  d_in[2];
    const float* emb      = (const float*)d_in[3];
    const float* w_ih     = (const float*)d_in[4];
    const float* b_ih     = (const float*)d_in[5];
    const float* w_hh     = (const float*)d_in[6];
    const float* b_hh     = (const float*)d_in[7];
    const float* w_init_h = (const float*)d_in[8];
    const float* b_init_h = (const float*)d_in[9];
    const float* w_init_c = (const float*)d_in[10];
    const float* b_init_c = (const float*)d_in[11];
    const float* w_fc     = (const float*)d_in[12];
    const float* b_fc     = (const float*)d_in[13];
    float* out = (float*)d_out;

    const long long pred_elems = (long long)NB * NT * VD;   // 96,000,000
    int extras = ((long long)out_size > pred_elems) ? 1 : 0;

    k_sort<<<1, 256>>>(clen, caps, out + pred_elems, extras);
    k_init<<<dim3(HD / 64, 1, 2), 256>>>(enc, w_init_h, b_init_h, w_init_c, b_init_c);
    k_xw<<<dim3(GD / 64, NT), 256>>>(emb, caps, w_ih, b_ih);
    for (int t = 0; t < NT; t++) {
        k_hh<<<dim3(GD / 64, 4), 256>>>(w_hh);
        k_point<<<128, 256>>>(b_hh, t);
    }
    k_fc<<<dim3((VD + 63) / 64, NT), 256>>>(w_fc, b_fc, out);
}

// round 5
// speedup vs baseline: 1.0003x; 1.0003x over previous
#include <cuda_runtime.h>
#include <math.h>

#define NB   64      // batch
#define CL   51      // caption length L
#define NT   50      // time steps T = L-1
#define ED   512     // embed dim E
#define HD   512     // hidden H
#define VD   30000   // vocab V
#define ENCD 2048    // encoder dim
#define GD   2048    // 4*H gates

// ---------------- device scratch (static, allocation-free) ----------------
__device__ int   g_sort[NB];
__device__ int   g_dlen[NB];
__device__ float g_h[NB * HD];
__device__ float g_c[NB * HD];
__device__ float g_XW[(size_t)NT * NB * GD];      // x@w_ih^T + b_ih, all steps (26 MB)
__device__ float g_parts[4][NB * GD];             // K-split partials of h@w_hh^T
__device__ float g_H[(size_t)NT * NB * HD];       // all hidden states (t,b,k)

// ---------------- common GEMM tile helpers (64x64 tile, BK=32, 4x4 micro) ----------------
__device__ __forceinline__ void stash_tile(float (*S)[65], int lr, int ls, float4 v0, float4 v1) {
    S[ls*4+0][lr] = v0.x; S[ls*4+1][lr] = v0.y; S[ls*4+2][lr] = v0.z; S[ls*4+3][lr] = v0.w;
    S[16+ls*4+0][lr] = v1.x; S[16+ls*4+1][lr] = v1.y; S[16+ls*4+2][lr] = v1.z; S[16+ls*4+3][lr] = v1.w;
}

__device__ __forceinline__ void mm_inner(float (*As)[65], float (*Bs)[65],
                                         float acc[4][4], int tx, int ty) {
#pragma unroll
    for (int kk = 0; kk < 32; kk++) {
        float a0 = As[kk][ty*4+0], a1 = As[kk][ty*4+1];
        float a2 = As[kk][ty*4+2], a3 = As[kk][ty*4+3];
        float b0 = Bs[kk][tx*4+0], b1 = Bs[kk][tx*4+1];
        float b2 = Bs[kk][tx*4+2], b3 = Bs[kk][tx*4+3];
        acc[0][0] += a0*b0; acc[0][1] += a0*b1; acc[0][2] += a0*b2; acc[0][3] += a0*b3;
        acc[1][0] += a1*b0; acc[1][1] += a1*b1; acc[1][2] += a1*b2; acc[1][3] += a1*b3;
        acc[2][0] += a2*b0; acc[2][1] += a2*b1; acc[2][2] += a2*b2; acc[2][3] += a2*b3;
        acc[3][0] += a3*b0; acc[3][1] += a3*b1; acc[3][2] += a3*b2; acc[3][3] += a3*b3;
    }
}

// ---------------- sort + extras ----------------
__global__ void k_sort(const int* __restrict__ lens, const int* __restrict__ caps,
                       float* __restrict__ out_extra, int extras) {
    __shared__ int slen[NB];
    __shared__ int sidx[NB];
    int t = threadIdx.x;
    if (t < NB) slen[t] = lens[t];
    __syncthreads();
    if (t < NB) {
        int Li = slen[t];
        int r = 0;
        for (int j = 0; j < NB; j++) {
            int Lj = slen[j];
            if (Lj > Li || (Lj == Li && j < t)) r++;   // stable descending
        }
        sidx[r] = t;
    }
    __syncthreads();
    if (t < NB) { g_sort[t] = sidx[t]; g_dlen[t] = slen[sidx[t]] - 1; }
    __syncthreads();
    if (extras) {
        for (int i = t; i < NB * CL; i += blockDim.x) {
            int b = i / CL, j = i % CL;
            out_extra[i] = (float)caps[sidx[b] * CL + j];
        }
        if (t < NB) out_extra[NB*CL + t]      = (float)(slen[sidx[t]] - 1);
        if (t < NB) out_extra[NB*CL + NB + t] = (float)sidx[t];
    }
}

// ---------------- init: h0 = enc_sorted @ w_init_h^T + b ; c0 likewise (blockIdx.z) ----------------
__global__ void k_init(const float* __restrict__ enc,
                       const float* __restrict__ wh, const float* __restrict__ bh,
                       const float* __restrict__ wc, const float* __restrict__ bc) {
    __shared__ float As[32][65], Bs[32][65];
    __shared__ int arow[64];
    const float* Wsel = blockIdx.z ? wc : wh;
    const float* bsel = blockIdx.z ? bc : bh;
    float* Csel = blockIdx.z ? g_c : g_h;
    int tid = threadIdx.x;
    if (tid < 64) arow[tid] = g_sort[tid];
    __syncthreads();
    int n0 = blockIdx.x * 64;
    int tx = tid & 15, ty = tid >> 4;
    int lr = tid >> 2, ls = tid & 3;
    float acc[4][4] = {};
    for (int k0 = 0; k0 < ENCD; k0 += 32) {
        const float4* ap = (const float4*)(enc + (size_t)arow[lr] * ENCD + k0);
        stash_tile(As, lr, ls, ap[ls], ap[ls + 4]);
        const float4* bp = (const float4*)(Wsel + (size_t)(n0 + lr) * ENCD + k0);
        stash_tile(Bs, lr, ls, bp[ls], bp[ls + 4]);
        __syncthreads();
        mm_inner(As, Bs, acc, tx, ty);
        __syncthreads();
    }
#pragma unroll
    for (int i = 0; i < 4; i++) {
        int m = ty*4 + i;
#pragma unroll
        for (int j = 0; j < 4; j++) {
            int n = n0 + tx*4 + j;
            Csel[m * HD + n] = acc[i][j] + bsel[n];
        }
    }
}

// ---------------- XW: all-steps input gates = emb_gather @ w_ih^T + b_ih ----------------
__global__ void k_xw(const float* __restrict__ emb, const int* __restrict__ caps,
                     const float* __restrict__ wih, const float* __restrict__ bih) {
    __shared__ float As[32][65], Bs[32][65];
    __shared__ int arow[64];
    int tid = threadIdx.x;
    int t = blockIdx.y;
    if (tid < 64) arow[tid] = caps[g_sort[tid] * CL + t];
    __syncthreads();
    int n0 = blockIdx.x * 64;
    int tx = tid & 15, ty = tid >> 4;
    int lr = tid >> 2, ls = tid & 3;
    float acc[4][4] = {};
    for (int k0 = 0; k0 < ED; k0 += 32) {
        const float4* ap = (const float4*)(emb + (size_t)arow[lr] * ED + k0);
        stash_tile(As, lr, ls, ap[ls], ap[ls + 4]);
        const float4* bp = (const float4*)(wih + (size_t)(n0 + lr) * ED + k0);
        stash_tile(Bs, lr, ls, bp[ls], bp[ls + 4]);
        __syncthreads();
        mm_inner(As, Bs, acc, tx, ty);
        __syncthreads();
    }
    float* outp = g_XW + ((size_t)t * NB) * GD;
#pragma unroll
    for (int i = 0; i < 4; i++) {
        int m = ty*4 + i;
#pragma unroll
        for (int j = 0; j < 4; j++) {
            int n = n0 + tx*4 + j;
            outp[(size_t)m * GD + n] = acc[i][j] + bih[n];
        }
    }
}

// ---------------- per-step: partial h @ w_hh^T (K split by 4 for parallelism) ----------------
__global__ void k_hh(const float* __restrict__ whh) {
    __shared__ float As[32][65], Bs[32][65];
    int tid = threadIdx.x;
    int n0 = blockIdx.x * 64;
    int kbase = blockIdx.y * 128;
    int tx = tid & 15, ty = tid >> 4;
    int lr = tid >> 2, ls = tid & 3;
    float acc[4][4] = {};
    for (int kc = 0; kc < 4; kc++) {
        int k0 = kbase + kc * 32;
        const float4* ap = (const float4*)(g_h + (size_t)lr * HD + k0);
        stash_tile(As, lr, ls, ap[ls], ap[ls + 4]);
        const float4* bp = (const float4*)(whh + (size_t)(n0 + lr) * HD + k0);
        stash_tile(Bs, lr, ls, bp[ls], bp[ls + 4]);
        __syncthreads();
        mm_inner(As, Bs, acc, tx, ty);
        __syncthreads();
    }
    float* outp = g_parts[blockIdx.y];
#pragma unroll
    for (int i = 0; i < 4; i++) {
        int m = ty*4 + i;
#pragma unroll
        for (int j = 0; j < 4; j++) {
            int n = n0 + tx*4 + j;
            outp[m * GD + n] = acc[i][j];
        }
    }
}

// ---------------- per-step: reduce partials + LSTM pointwise ----------------
__global__ void k_point(const float* __restrict__ bhh, int t) {
    int idx = blockIdx.x * blockDim.x + threadIdx.x;   // 128*256 = 32768 = NB*HD
    int b = idx >> 9, j = idx & 511;
    const float* xw = g_XW + ((size_t)t * NB + b) * GD;
    float gi = xw[j]          + bhh[j];
    float gf = xw[512 + j]    + bhh[512 + j];
    float gg = xw[1024 + j]   + bhh[1024 + j];
    float go = xw[1536 + j]   + bhh[1536 + j];
#pragma unroll
    for (int p = 0; p < 4; p++) {
        const float* pp = g_parts[p] + b * GD;
        gi += pp[j]; gf += pp[512 + j]; gg += pp[1024 + j]; go += pp[1536 + j];
    }
    float c = g_c[b * HD + j];
    float si = 1.f / (1.f + expf(-gi));
    float sf = 1.f / (1.f + expf(-gf));
    float so = 1.f / (1.f + expf(-go));
    c = sf * c + si * tanhf(gg);
    float h = so * tanhf(c);
    g_c[b * HD + j] = c;
    g_h[b * HD + j] = h;
    g_H[((size_t)t * NB + b) * HD + j] = h;
}

// ---------------- big FC: preds = H_all @ w_fc^T + b_fc, masked ----------------
__global__ void k_fc(const float* __restrict__ wfc, const float* __restrict__ bfc,
                     float* __restrict__ out) {
    __shared__ float As[32][65], Bs[32][65];
    int tid = threadIdx.x;
    int n0 = blockIdx.x * 64;
    int t = blockIdx.y;
    int tx = tid & 15, ty = tid >> 4;
    int lr = tid >> 2, ls = tid & 3;
    int w = tid >> 5;
    // warps cover 8 consecutive batch rows; lengths sorted desc -> prefix active
    bool wact = (g_dlen[w * 8] > t);
    float acc[4][4] = {};
    const float* Abase = g_H + (size_t)t * NB * HD;
    for (int k0 = 0; k0 < HD; k0 += 32) {
        const float4* ap = (const float4*)(Abase + (size_t)lr * HD + k0);
        stash_tile(As, lr, ls, ap[ls], ap[ls + 4]);
        int nr = n0 + lr;
        float4 b0 = make_float4(0.f, 0.f, 0.f, 0.f), b1 = b0;
        if (nr < VD) {
            const float4* bp = (const float4*)(wfc + (size_t)nr * HD + k0);
            b0 = bp[ls]; b1 = bp[ls + 4];
        }
        stash_tile(Bs, lr, ls, b0, b1);
        __syncthreads();
        if (wact) mm_inner(As, Bs, acc, tx, ty);
        __syncthreads();
    }
#pragma unroll
    for (int i = 0; i < 4; i++) {
        int m = ty*4 + i;
        bool act = (g_dlen[m] > t);
#pragma unroll
        for (int j = 0; j < 4; j++) {
            int n = n0 + tx*4 + j;
            if (n < VD) {
                size_t o = (size_t)m * ((size_t)NT * VD) + (size_t)t * VD + n;
                out[o] = act ? (acc[i][j] + bfc[n]) : 0.0f;
            }
        }
    }
}

// ---------------- launch ----------------
extern "C" void kernel_launch(void* const* d_in, const int* in_sizes, int n_in,
                              void* d_out, int out_size) {
    const float* enc      = (const float*)d_in[0];
    const int*   caps     = (const int*)  d_in[1];
    const int*   clen     = (const int*)  d_in[2];
    const float* emb      = (const float*)d_in[3];
    const float* w_ih     = (const float*)d_in[4];
    const float* b_ih     = (const float*)d_in[5];
    const float* w_hh     = (const float*)d_in[6];
    const float* b_hh     = (const float*)d_in[7];
    const float* w_init_h = (const float*)d_in[8];
    const float* b_init_h = (const float*)d_in[9];
    const float* w_init_c = (const float*)d_in[10];
    const float* b_init_c = (const float*)d_in[11];
    const float* w_fc     = (const float*)d_in[12];
    const float* b_fc     = (const float*)d_in[13];
    float* out = (float*)d_out;

    const long long pred_elems = (long long)NB * NT * VD;   // 96,000,000
    int extras = ((long long)out_size > pred_elems) ? 1 : 0;

    k_sort<<<1, 256>>>(clen, caps, out + pred_elems, extras);
    k_init<<<dim3(HD / 64, 1, 2), 256>>>(enc, w_init_h, b_init_h, w_init_c, b_init_c);
    k_xw<<<dim3(GD / 64, NT), 256>>>(emb, caps, w_ih, b_ih);
    for (int t = 0; t < NT; t++) {
        k_hh<<<dim3(GD / 64, 4), 256>>>(w_hh);
        k_point<<<128, 256>>>(b_hh, t);
    }
    k_fc<<<dim3((VD + 63) / 64, NT), 256>>>(w_fc, b_fc, out);
}

// round 10
// speedup vs baseline: 1.5998x; 1.5993x over previous
#include <cuda_runtime.h>
#include <cuda_bf16.h>
#include <math.h>
#include <stdint.h>

#define NB   64
#define CL   51
#define NT   50
#define ED   512
#define HD   512
#define VD   30000
#define ENCD 2048
#define GD   2048

#define MT   25      // M tiles (128 rows) of H (3200 = 50t x 64b, t-major)
#define NTB  235     // N tiles (128 vocab rows) -> 30080 padded
#define KC   8       // K chunks of 64
#define RB   128     // persistent rnn blocks

// ---------------- device scratch ----------------
__device__ int      g_sort[NB];
__device__ int      g_dlen[NB];
__device__ float    g_h[NB * HD];
__device__ float    g_c[NB * HD];
__device__ float    g_XW[(size_t)NT * NB * GD];
__device__ float    g_gates[NB * GD];
__device__ float    g_H[(size_t)NT * NB * HD];
__device__ unsigned g_cnt;
__device__ unsigned g_phase;

// packed bf16 SW128-swizzled tiles: [tile][kc][128 rows x 64 k] = 8192 bf16 (16KB)
__device__ __align__(128) __nv_bfloat16 g_Bhi[(size_t)NTB * KC * 8192];
__device__ __align__(128) __nv_bfloat16 g_Blo[(size_t)NTB * KC * 8192];
__device__ __align__(128) __nv_bfloat16 g_Ahi[(size_t)MT  * KC * 8192];
__device__ __align__(128) __nv_bfloat16 g_Alo[(size_t)MT  * KC * 8192];

// ---------------- PTX helpers (baseline sm_80-level only) ----------------
__device__ __forceinline__ uint32_t s2u(const void* p) {
    uint32_t a;
    asm("{ .reg .u64 t; cvta.to.shared.u64 t, %1; cvt.u32.u64 %0, t; }" : "=r"(a) : "l"(p));
    return a;
}
__device__ __forceinline__ void cp16(uint32_t d, const void* s) {
    asm volatile("cp.async.cg.shared.global [%0], [%1], 16;" :: "r"(d), "l"(s));
}
#define LDSM4(r0, r1, r2, r3, addr) \
    asm volatile("ldmatrix.sync.aligned.m8n8.x4.shared.b16 {%0,%1,%2,%3}, [%4];" \
        : "=r"(r0), "=r"(r1), "=r"(r2), "=r"(r3) : "r"(addr))
#define MMA16816(d, a, b) \
    asm volatile("mma.sync.aligned.m16n8k16.row.col.f32.bf16.bf16.f32 " \
        "{%0,%1,%2,%3},{%4,%5,%6,%7},{%8,%9},{%0,%1,%2,%3};" \
        : "+f"((d)[0]), "+f"((d)[1]), "+f"((d)[2]), "+f"((d)[3]) \
        : "r"((a)[0]), "r"((a)[1]), "r"((a)[2]), "r"((a)[3]), "r"((b)[0]), "r"((b)[1]))

// ---------------- fp32 GEMM tile helpers (small GEMMs) ----------------
__device__ __forceinline__ void stash_tile(float (*S)[65], int lr, int ls, float4 v0, float4 v1) {
    S[ls*4+0][lr] = v0.x; S[ls*4+1][lr] = v0.y; S[ls*4+2][lr] = v0.z; S[ls*4+3][lr] = v0.w;
    S[16+ls*4+0][lr] = v1.x; S[16+ls*4+1][lr] = v1.y; S[16+ls*4+2][lr] = v1.z; S[16+ls*4+3][lr] = v1.w;
}
__device__ __forceinline__ void mm_inner(float (*As)[65], float (*Bs)[65],
                                         float acc[4][4], int tx, int ty) {
#pragma unroll
    for (int kk = 0; kk < 32; kk++) {
        float a0 = As[kk][ty*4+0], a1 = As[kk][ty*4+1];
        float a2 = As[kk][ty*4+2], a3 = As[kk][ty*4+3];
        float b0 = Bs[kk][tx*4+0], b1 = Bs[kk][tx*4+1];
        float b2 = Bs[kk][tx*4+2], b3 = Bs[kk][tx*4+3];
        acc[0][0] += a0*b0; acc[0][1] += a0*b1; acc[0][2] += a0*b2; acc[0][3] += a0*b3;
        acc[1][0] += a1*b0; acc[1][1] += a1*b1; acc[1][2] += a1*b2; acc[1][3] += a1*b3;
        acc[2][0] += a2*b0; acc[2][1] += a2*b1; acc[2][2] += a2*b2; acc[2][3] += a2*b3;
        acc[3][0] += a3*b0; acc[3][1] += a3*b1; acc[3][2] += a3*b2; acc[3][3] += a3*b3;
    }
}

// ---------------- sort + extras ----------------
__global__ void k_sort(const int* __restrict__ lens, const int* __restrict__ caps,
                       float* __restrict__ out_extra, int extras) {
    __shared__ int slen[NB];
    __shared__ int sidx[NB];
    int t = threadIdx.x;
    if (t < NB) slen[t] = lens[t];
    __syncthreads();
    if (t < NB) {
        int Li = slen[t];
        int r = 0;
        for (int j = 0; j < NB; j++) {
            int Lj = slen[j];
            if (Lj > Li || (Lj == Li && j < t)) r++;
        }
        sidx[r] = t;
    }
    __syncthreads();
    if (t < NB) { g_sort[t] = sidx[t]; g_dlen[t] = slen[sidx[t]] - 1; }
    __syncthreads();
    if (extras) {
        for (int i = t; i < NB * CL; i += blockDim.x) {
            int b = i / CL, j = i % CL;
            out_extra[i] = (float)caps[sidx[b] * CL + j];
        }
        if (t < NB) out_extra[NB*CL + t]      = (float)(slen[sidx[t]] - 1);
        if (t < NB) out_extra[NB*CL + NB + t] = (float)sidx[t];
    }
}

// ---------------- pack w_fc -> swizzled bf16 hi/lo (128-row tiles) ----------------
__global__ void k_packB(const float* __restrict__ wfc) {
    int tile = blockIdx.x, kc = blockIdx.y;
    size_t base = ((size_t)tile * KC + kc) * 8192;
    for (int i = threadIdx.x; i < 8192; i += 256) {
        int r = i >> 6, c = i & 63;
        int n = tile * 128 + r;
        float v = (n < VD) ? wfc[(size_t)n * HD + kc * 64 + c] : 0.f;
        __nv_bfloat16 hi = __float2bfloat16(v);
        __nv_bfloat16 lo = __float2bfloat16(v - __bfloat162float(hi));
        uint32_t off = (uint32_t)r * 128 + c * 2;
        uint32_t sw = off ^ ((off >> 3) & 0x70);
        g_Bhi[base + (sw >> 1)] = hi;
        g_Blo[base + (sw >> 1)] = lo;
    }
}

// ---------------- pack g_H -> swizzled bf16 hi/lo (t-major rows) ----------------
__global__ void k_packA() {
    int tile = blockIdx.x, kc = blockIdx.y;
    size_t base = ((size_t)tile * KC + kc) * 8192;
    for (int i = threadIdx.x; i < 8192; i += 256) {
        int r = i >> 6, c = i & 63;
        int t = tile * 2 + (r >> 6), b = r & 63;
        float v = g_H[((size_t)t * NB + b) * HD + kc * 64 + c];
        __nv_bfloat16 hi = __float2bfloat16(v);
        __nv_bfloat16 lo = __float2bfloat16(v - __bfloat162float(hi));
        uint32_t off = (uint32_t)r * 128 + c * 2;
        uint32_t sw = off ^ ((off >> 3) & 0x70);
        g_Ahi[base + (sw >> 1)] = hi;
        g_Alo[base + (sw >> 1)] = lo;
    }
}

// ---------------- init h0/c0 ----------------
__global__ void k_init(const float* __restrict__ enc,
                       const float* __restrict__ wh, const float* __restrict__ bh,
                       const float* __restrict__ wc, const float* __restrict__ bc) {
    __shared__ float As[32][65], Bs[32][65];
    __shared__ int arow[64];
    const float* Wsel = blockIdx.z ? wc : wh;
    const float* bsel = blockIdx.z ? bc : bh;
    float* Csel = blockIdx.z ? g_c : g_h;
    int tid = threadIdx.x;
    if (tid < 64) arow[tid] = g_sort[tid];
    __syncthreads();
    int n0 = blockIdx.x * 64;
    int tx = tid & 15, ty = tid >> 4;
    int lr = tid >> 2, ls = tid & 3;
    float acc[4][4] = {};
    for (int k0 = 0; k0 < ENCD; k0 += 32) {
        const float4* ap = (const float4*)(enc + (size_t)arow[lr] * ENCD + k0);
        stash_tile(As, lr, ls, ap[ls], ap[ls + 4]);
        const float4* bp = (const float4*)(Wsel + (size_t)(n0 + lr) * ENCD + k0);
        stash_tile(Bs, lr, ls, bp[ls], bp[ls + 4]);
        __syncthreads();
        mm_inner(As, Bs, acc, tx, ty);
        __syncthreads();
    }
#pragma unroll
    for (int i = 0; i < 4; i++) {
        int m = ty*4 + i;
#pragma unroll
        for (int j = 0; j < 4; j++) {
            int n = n0 + tx*4 + j;
            Csel[m * HD + n] = acc[i][j] + bsel[n];
        }
    }
}

// ---------------- XW: all-steps input gates ----------------
__global__ void k_xw(const float* __restrict__ emb, const int* __restrict__ caps,
                     const float* __restrict__ wih, const float* __restrict__ bih) {
    __shared__ float As[32][65], Bs[32][65];
    __shared__ int arow[64];
    int tid = threadIdx.x;
    int t = blockIdx.y;
    if (tid < 64) arow[tid] = caps[g_sort[tid] * CL + t];
    __syncthreads();
    int n0 = blockIdx.x * 64;
    int tx = tid & 15, ty = tid >> 4;
    int lr = tid >> 2, ls = tid & 3;
    float acc[4][4] = {};
    for (int k0 = 0; k0 < ED; k0 += 32) {
        const float4* ap = (const float4*)(emb + (size_t)arow[lr] * ED + k0);
        stash_tile(As, lr, ls, ap[ls], ap[ls + 4]);
        const float4* bp = (const float4*)(wih + (size_t)(n0 + lr) * ED + k0);
        stash_tile(Bs, lr, ls, bp[ls], bp[ls + 4]);
        __syncthreads();
        mm_inner(As, Bs, acc, tx, ty);
        __syncthreads();
    }
    float* outp = g_XW + ((size_t)t * NB) * GD;
#pragma unroll
    for (int i = 0; i < 4; i++) {
        int m = ty*4 + i;
#pragma unroll
        for (int j = 0; j < 4; j++) {
            int n = n0 + tx*4 + j;
            outp[(size_t)m * GD + n] = acc[i][j] + bih[n];
        }
    }
}

// ---------------- persistent recurrence: 50 steps in one launch ----------------
__device__ __forceinline__ void gsync(unsigned target) {
    __syncthreads();
    if (threadIdx.x == 0) {
        __threadfence();
        unsigned old = atomicAdd(&g_cnt, 1);
        if (old == RB - 1) {
            atomicExch(&g_cnt, 0);
            __threadfence();
            atomicAdd(&g_phase, 1);
        } else {
            while ((int)(*(volatile unsigned*)&g_phase - target) < 0) {}
        }
    }
    __syncthreads();
}

__global__ void __launch_bounds__(256, 1) k_rnn(const float* __restrict__ whh,
                                                const float* __restrict__ bhh) {
    extern __shared__ float sm[];
    float* w_s = sm;               // [k][16]  512*16
    float* h_s = sm + 512 * 16;    // [b][516] padded rows
    int tid = threadIdx.x, bi = blockIdx.x;
    int n0 = bi * 16;
    for (int idx = tid; idx < 16 * 512; idx += 256) {
        int r = idx >> 9, k = idx & 511;
        w_s[k * 16 + r] = whh[(size_t)(n0 + r) * HD + k];
    }
    int gb = tid >> 2, gn = (tid & 3) * 4;          // gemm: out (gb, n0+gn..+3)
    int pb = tid >> 2, pj = bi * 4 + (tid & 3);     // pointwise: (pb, pj)
    float c_reg = g_c[pb * HD + pj];
    float4 bh4 = *(const float4*)&bhh[n0 + gn];
    unsigned base = *(volatile unsigned*)&g_phase;
    unsigned lp = 0;
    __syncthreads();
    for (int t = 0; t < NT; t++) {
        // stage h (written by other SMs last step) -> smem, bypass L1
        for (int idx = tid; idx < (NB * HD) / 4; idx += 256) {
            int lin = idx * 4;
            int b = lin >> 9, k = lin & 511;
            float4 hv = __ldcg((const float4*)&g_h[b * HD + k]);
            *(float4*)&h_s[b * 516 + k] = hv;
        }
        __syncthreads();
        float a0 = 0.f, a1 = 0.f, a2 = 0.f, a3 = 0.f;
        const float* hrow = &h_s[gb * 516];
#pragma unroll 8
        for (int k = 0; k < 512; k++) {
            float h = hrow[k];
            float4 w = *(const float4*)&w_s[k * 16 + gn];
            a0 += h * w.x; a1 += h * w.y; a2 += h * w.z; a3 += h * w.w;
        }
        float4 xv = __ldg((const float4*)&g_XW[((size_t)t * NB + gb) * GD + n0 + gn]);
        float4 gv = make_float4(a0 + xv.x + bh4.x, a1 + xv.y + bh4.y,
                                a2 + xv.z + bh4.z, a3 + xv.w + bh4.w);
        __stcg((float4*)&g_gates[gb * GD + n0 + gn], gv);
        gsync(base + (++lp));
        // pointwise LSTM update
        float gi = __ldcg(&g_gates[pb * GD + pj]);
        float gf = __ldcg(&g_gates[pb * GD + 512 + pj]);
        float gg = __ldcg(&g_gates[pb * GD + 1024 + pj]);
        float go = __ldcg(&g_gates[pb * GD + 1536 + pj]);
        float si = 1.f / (1.f + expf(-gi));
        float sf = 1.f / (1.f + expf(-gf));
        float so = 1.f / (1.f + expf(-go));
        c_reg = sf * c_reg + si * tanhf(gg);
        float hv = so * tanhf(c_reg);
        __stcg(&g_h[pb * HD + pj], hv);
        __stcg(&g_H[((size_t)t * NB + pb) * HD + pj], hv);
        gsync(base + (++lp));
        __syncthreads();   // h_s reuse safety (all threads past gemm reads)
    }
}

// ---------------- FC on mma.sync bf16: 128x128 block tile, 3-term ----------------
__device__ __forceinline__ void fc_load(uint32_t st, int mtile, int ntile, int c, int tid) {
    const char* s0 = (const char*)(g_Ahi + ((size_t)mtile * KC + c) * 8192);
    const char* s1 = (const char*)(g_Alo + ((size_t)mtile * KC + c) * 8192);
    const char* s2 = (const char*)(g_Bhi + ((size_t)ntile * KC + c) * 8192);
    const char* s3 = (const char*)(g_Blo + ((size_t)ntile * KC + c) * 8192);
#pragma unroll
    for (int i = tid * 16; i < 16384; i += 4096) {
        cp16(st + i,         s0 + i);
        cp16(st + 16384 + i, s1 + i);
        cp16(st + 32768 + i, s2 + i);
        cp16(st + 49152 + i, s3 + i);
    }
    asm volatile("cp.async.commit_group;" ::: "memory");
}

__global__ void __launch_bounds__(256, 1)
k_fc_mma(const float* __restrict__ bfc, float* __restrict__ out) {
    extern __shared__ char smem[];
    uint32_t sb = s2u(smem);
    int tid = threadIdx.x;
    int lane = tid & 31, warp = tid >> 5;
    int warp_m = warp & 3, warp_n = warp >> 2;
    int m0 = warp_m * 32, n0w = warp_n * 64;
    int mtile = blockIdx.x % MT, ntile = blockIdx.x / MT;

    // fragment activity (rows t-major; active batches form a prefix)
    int g0 = mtile * 128 + m0;
    int t_f = g0 >> 6, b_f = g0 & 63;
    bool mact[2];
    mact[0] = (__ldg(&g_dlen[b_f]) > t_f);
    mact[1] = (__ldg(&g_dlen[b_f + 16]) > t_f);

    int rl = lane & 7, q = lane >> 3;
    float acc[2][8][4];
#pragma unroll
    for (int f = 0; f < 2; f++)
#pragma unroll
        for (int nf = 0; nf < 8; nf++)
#pragma unroll
            for (int e = 0; e < 4; e++) acc[f][nf][e] = 0.f;

    fc_load(sb, mtile, ntile, 0, tid);
    for (int c = 0; c < KC; c++) {
        asm volatile("cp.async.wait_group 0;" ::: "memory");
        __syncthreads();
        if (c + 1 < KC)
            fc_load(sb + (uint32_t)((c + 1) & 1) * 65536, mtile, ntile, c + 1, tid);
        uint32_t stA  = sb + (uint32_t)(c & 1) * 65536;
        uint32_t stAl = stA + 16384, stB = stA + 32768, stBl = stA + 49152;
#pragma unroll
        for (int s = 0; s < 4; s++) {
            uint32_t bh[8][2], bl[8][2];
#pragma unroll
            for (int g = 0; g < 4; g++) {
                int row = n0w + g * 16 + ((q >> 1) << 3) + rl;
                int off = row * 128 + s * 32 + ((q & 1) << 4);
                int sw = off ^ ((off >> 3) & 0x70);
                uint32_t r0, r1, r2, r3;
                LDSM4(r0, r1, r2, r3, stB + sw);
                bh[g*2][0] = r0; bh[g*2][1] = r1; bh[g*2+1][0] = r2; bh[g*2+1][1] = r3;
                LDSM4(r0, r1, r2, r3, stBl + sw);
                bl[g*2][0] = r0; bl[g*2][1] = r1; bl[g*2+1][0] = r2; bl[g*2+1][1] = r3;
            }
#pragma unroll
            for (int f = 0; f < 2; f++) {
                if (!mact[f]) continue;
                int row = m0 + f * 16 + rl + ((q & 1) << 3);
                int off = row * 128 + s * 32 + ((q >> 1) << 4);
                int sw = off ^ ((off >> 3) & 0x70);
                uint32_t ah[4], al[4];
                LDSM4(ah[0], ah[1], ah[2], ah[3], stA + sw);
                LDSM4(al[0], al[1], al[2], al[3], stAl + sw);
#pragma unroll
                for (int nf = 0; nf < 8; nf++) {
                    MMA16816(acc[f][nf], ah, bh[nf]);
                    MMA16816(acc[f][nf], ah, bl[nf]);
                    MMA16816(acc[f][nf], al, bh[nf]);
                }
            }
        }
        __syncthreads();
    }

    // epilogue: direct masked stores, out[b][t][n]
#pragma unroll
    for (int f = 0; f < 2; f++) {
        int rbase = mtile * 128 + m0 + f * 16 + (lane >> 2);
#pragma unroll
        for (int rr = 0; rr < 2; rr++) {
            int r = rbase + rr * 8;
            int t = r >> 6, b = r & 63;
            bool act = (__ldg(&g_dlen[b]) > t);
            float* orow = out + ((size_t)b * NT + t) * VD;
#pragma unroll
            for (int nf = 0; nf < 8; nf++) {
                int n = ntile * 128 + n0w + nf * 8 + ((lane & 3) << 1);
                if (n < VD) {
                    float2 v;
                    if (act) {
                        float2 bb = __ldg((const float2*)&bfc[n]);
                        v.x = acc[f][nf][rr * 2 + 0] + bb.x;
                        v.y = acc[f][nf][rr * 2 + 1] + bb.y;
                    } else { v.x = 0.f; v.y = 0.f; }
                    *(float2*)&orow[n] = v;
                }
            }
        }
    }
}

// ---------------- launch ----------------
extern "C" void kernel_launch(void* const* d_in, const int* in_sizes, int n_in,
                              void* d_out, int out_size) {
    const float* enc      = (const float*)d_in[0];
    const int*   caps     = (const int*)  d_in[1];
    const int*   clen     = (const int*)  d_in[2];
    const float* emb      = (const float*)d_in[3];
    const float* w_ih     = (const float*)d_in[4];
    const float* b_ih     = (const float*)d_in[5];
    const float* w_hh     = (const float*)d_in[6];
    const float* b_hh     = (const float*)d_in[7];
    const float* w_init_h = (const float*)d_in[8];
    const float* b_init_h = (const float*)d_in[9];
    const float* w_init_c = (const float*)d_in[10];
    const float* b_init_c = (const float*)d_in[11];
    const float* w_fc     = (const float*)d_in[12];
    const float* b_fc     = (const float*)d_in[13];
    float* out = (float*)d_out;

    const long long pred_elems = (long long)NB * NT * VD;
    int extras = ((long long)out_size > pred_elems) ? 1 : 0;

    const int rnn_smem = (512 * 16 + 64 * 516) * 4;   // 164864
    const int fc_smem  = 2 * 65536;                   // 131072
    cudaFuncSetAttribute(k_rnn,    cudaFuncAttributeMaxDynamicSharedMemorySize, rnn_smem);
    cudaFuncSetAttribute(k_fc_mma, cudaFuncAttributeMaxDynamicSharedMemorySize, fc_smem);

    k_sort<<<1, 256>>>(clen, caps, out + pred_elems, extras);
    k_packB<<<dim3(NTB, KC), 256>>>(w_fc);
    k_init<<<dim3(HD / 64, 1, 2), 256>>>(enc, w_init_h, b_init_h, w_init_c, b_init_c);
    k_xw<<<dim3(GD / 64, NT), 256>>>(emb, caps, w_ih, b_ih);
    k_rnn<<<RB, 256, rnn_smem>>>(w_hh, b_hh);
    k_packA<<<dim3(MT, KC), 256>>>();
    k_fc_mma<<<MT * NTB, 256, fc_smem>>>(b_fc, out);
}

// round 11
// speedup vs baseline: 1.8575x; 1.1611x over previous
#include <cuda_runtime.h>
#include <cuda_bf16.h>
#include <math.h>
#include <stdint.h>

#define NB   64
#define CL   51
#define NT   50
#define ED   512
#define HD   512
#define VD   30000
#define ENCD 2048
#define GD   2048

#define MT   25      // M tiles (128 rows) of H (3200 = 50t x 64b, t-major)
#define NTB  235     // FC N tiles (128 vocab rows) -> 30080 padded
#define NTW  16      // XW N tiles (2048 / 128)
#define KC   8       // K chunks of 64
#define RB   128     // persistent rnn blocks

// ---------------- device scratch ----------------
__device__ int      g_sort[NB];
__device__ int      g_dlen[NB];
__device__ float    g_h[NB * HD];
__device__ float    g_c[NB * HD];
__device__ float    g_XW[(size_t)NT * NB * GD];
__device__ float    g_gates[NB * GD];
__device__ float    g_H[(size_t)NT * NB * HD];
__device__ float    g_ip[16][NB * HD];
__device__ unsigned g_cnt;
__device__ unsigned g_phase;

// packed bf16 SW128-swizzled tiles: [tile][kc][128 rows x 64 k] = 8192 bf16 (16KB)
__device__ __align__(128) __nv_bfloat16 g_Bhi[(size_t)NTB * KC * 8192];
__device__ __align__(128) __nv_bfloat16 g_Blo[(size_t)NTB * KC * 8192];
__device__ __align__(128) __nv_bfloat16 g_Ahi[(size_t)MT  * KC * 8192];
__device__ __align__(128) __nv_bfloat16 g_Alo[(size_t)MT  * KC * 8192];
__device__ __align__(128) __nv_bfloat16 g_Whi[(size_t)NTW * KC * 8192];
__device__ __align__(128) __nv_bfloat16 g_Wlo[(size_t)NTW * KC * 8192];
__device__ __align__(128) __nv_bfloat16 g_Ehi[(size_t)MT  * KC * 8192];
__device__ __align__(128) __nv_bfloat16 g_Elo[(size_t)MT  * KC * 8192];

// ---------------- PTX helpers (baseline sm_80-level only) ----------------
__device__ __forceinline__ uint32_t s2u(const void* p) {
    uint32_t a;
    asm("{ .reg .u64 t; cvta.to.shared.u64 t, %1; cvt.u32.u64 %0, t; }" : "=r"(a) : "l"(p));
    return a;
}
__device__ __forceinline__ void cp16(uint32_t d, const void* s) {
    asm volatile("cp.async.cg.shared.global [%0], [%1], 16;" :: "r"(d), "l"(s));
}
#define LDSM4(r0, r1, r2, r3, addr) \
    asm volatile("ldmatrix.sync.aligned.m8n8.x4.shared.b16 {%0,%1,%2,%3}, [%4];" \
        : "=r"(r0), "=r"(r1), "=r"(r2), "=r"(r3) : "r"(addr))
#define MMA16816(d, a, b) \
    asm volatile("mma.sync.aligned.m16n8k16.row.col.f32.bf16.bf16.f32 " \
        "{%0,%1,%2,%3},{%4,%5,%6,%7},{%8,%9},{%0,%1,%2,%3};" \
        : "+f"((d)[0]), "+f"((d)[1]), "+f"((d)[2]), "+f"((d)[3]) \
        : "r"((a)[0]), "r"((a)[1]), "r"((a)[2]), "r"((a)[3]), "r"((b)[0]), "r"((b)[1]))

// ---------------- fp32 GEMM tile helpers (init GEMM) ----------------
__device__ __forceinline__ void stash_tile(float (*S)[65], int lr, int ls, float4 v0, float4 v1) {
    S[ls*4+0][lr] = v0.x; S[ls*4+1][lr] = v0.y; S[ls*4+2][lr] = v0.z; S[ls*4+3][lr] = v0.w;
    S[16+ls*4+0][lr] = v1.x; S[16+ls*4+1][lr] = v1.y; S[16+ls*4+2][lr] = v1.z; S[16+ls*4+3][lr] = v1.w;
}
__device__ __forceinline__ void mm_inner(float (*As)[65], float (*Bs)[65],
                                         float acc[4][4], int tx, int ty) {
#pragma unroll
    for (int kk = 0; kk < 32; kk++) {
        float a0 = As[kk][ty*4+0], a1 = As[kk][ty*4+1];
        float a2 = As[kk][ty*4+2], a3 = As[kk][ty*4+3];
        float b0 = Bs[kk][tx*4+0], b1 = Bs[kk][tx*4+1];
        float b2 = Bs[kk][tx*4+2], b3 = Bs[kk][tx*4+3];
        acc[0][0] += a0*b0; acc[0][1] += a0*b1; acc[0][2] += a0*b2; acc[0][3] += a0*b3;
        acc[1][0] += a1*b0; acc[1][1] += a1*b1; acc[1][2] += a1*b2; acc[1][3] += a1*b3;
        acc[2][0] += a2*b0; acc[2][1] += a2*b1; acc[2][2] += a2*b2; acc[2][3] += a2*b3;
        acc[3][0] += a3*b0; acc[3][1] += a3*b1; acc[3][2] += a3*b2; acc[3][3] += a3*b3;
    }
}

// ---------------- sort + extras ----------------
__global__ void k_sort(const int* __restrict__ lens, const int* __restrict__ caps,
                       float* __restrict__ out_extra, int extras) {
    __shared__ int slen[NB];
    __shared__ int sidx[NB];
    int t = threadIdx.x;
    if (t < NB) slen[t] = lens[t];
    __syncthreads();
    if (t < NB) {
        int Li = slen[t];
        int r = 0;
        for (int j = 0; j < NB; j++) {
            int Lj = slen[j];
            if (Lj > Li || (Lj == Li && j < t)) r++;
        }
        sidx[r] = t;
    }
    __syncthreads();
    if (t < NB) { g_sort[t] = sidx[t]; g_dlen[t] = slen[sidx[t]] - 1; }
    __syncthreads();
    if (extras) {
        for (int i = t; i < NB * CL; i += blockDim.x) {
            int b = i / CL, j = i % CL;
            out_extra[i] = (float)caps[sidx[b] * CL + j];
        }
        if (t < NB) out_extra[NB*CL + t]      = (float)(slen[sidx[t]] - 1);
        if (t < NB) out_extra[NB*CL + NB + t] = (float)sidx[t];
    }
}

// ---------------- packers: fp32 -> swizzled bf16 hi/lo (128-row x 64-k tiles) ----------------
__global__ void k_packB(const float* __restrict__ wfc) {
    int tile = blockIdx.x, kc = blockIdx.y;
    size_t base = ((size_t)tile * KC + kc) * 8192;
    for (int i = threadIdx.x; i < 8192; i += 256) {
        int r = i >> 6, c = i & 63;
        int n = tile * 128 + r;
        float v = (n < VD) ? wfc[(size_t)n * HD + kc * 64 + c] : 0.f;
        __nv_bfloat16 hi = __float2bfloat16(v);
        __nv_bfloat16 lo = __float2bfloat16(v - __bfloat162float(hi));
        uint32_t off = (uint32_t)r * 128 + c * 2;
        uint32_t sw = off ^ ((off >> 3) & 0x70);
        g_Bhi[base + (sw >> 1)] = hi;
        g_Blo[base + (sw >> 1)] = lo;
    }
}

__global__ void k_packW(const float* __restrict__ wih) {
    int tile = blockIdx.x, kc = blockIdx.y;
    size_t base = ((size_t)tile * KC + kc) * 8192;
    for (int i = threadIdx.x; i < 8192; i += 256) {
        int r = i >> 6, c = i & 63;
        int n = tile * 128 + r;
        float v = wih[(size_t)n * ED + kc * 64 + c];
        __nv_bfloat16 hi = __float2bfloat16(v);
        __nv_bfloat16 lo = __float2bfloat16(v - __bfloat162float(hi));
        uint32_t off = (uint32_t)r * 128 + c * 2;
        uint32_t sw = off ^ ((off >> 3) & 0x70);
        g_Whi[base + (sw >> 1)] = hi;
        g_Wlo[base + (sw >> 1)] = lo;
    }
}

// gathered sorted embedding rows (t-major rows, gather folded into pack; after k_sort)
__global__ void k_packE(const float* __restrict__ emb, const int* __restrict__ caps) {
    int tile = blockIdx.x, kc = blockIdx.y;
    __shared__ int tok[128];
    size_t base = ((size_t)tile * KC + kc) * 8192;
    if (threadIdx.x < 128) {
        int r = threadIdx.x;
        int t = tile * 2 + (r >> 6), b = r & 63;
        tok[r] = caps[g_sort[b] * CL + t];
    }
    __syncthreads();
    for (int i = threadIdx.x; i < 8192; i += 256) {
        int r = i >> 6, c = i & 63;
        float v = emb[(size_t)tok[r] * ED + kc * 64 + c];
        __nv_bfloat16 hi = __float2bfloat16(v);
        __nv_bfloat16 lo = __float2bfloat16(v - __bfloat162float(hi));
        uint32_t off = (uint32_t)r * 128 + c * 2;
        uint32_t sw = off ^ ((off >> 3) & 0x70);
        g_Ehi[base + (sw >> 1)] = hi;
        g_Elo[base + (sw >> 1)] = lo;
    }
}

__global__ void k_packA() {
    int tile = blockIdx.x, kc = blockIdx.y;
    size_t base = ((size_t)tile * KC + kc) * 8192;
    for (int i = threadIdx.x; i < 8192; i += 256) {
        int r = i >> 6, c = i & 63;
        int t = tile * 2 + (r >> 6), b = r & 63;
        float v = g_H[((size_t)t * NB + b) * HD + kc * 64 + c];
        __nv_bfloat16 hi = __float2bfloat16(v);
        __nv_bfloat16 lo = __float2bfloat16(v - __bfloat162float(hi));
        uint32_t off = (uint32_t)r * 128 + c * 2;
        uint32_t sw = off ^ ((off >> 3) & 0x70);
        g_Ahi[base + (sw >> 1)] = hi;
        g_Alo[base + (sw >> 1)] = lo;
    }
}

// ---------------- init h0/c0: K-split partials + fused reduce ----------------
__global__ void k_init_part(const float* __restrict__ enc,
                            const float* __restrict__ wh, const float* __restrict__ wc) {
    __shared__ float As[32][65], Bs[32][65];
    __shared__ int arow[64];
    const float* Wsel = blockIdx.z ? wc : wh;
    int tid = threadIdx.x;
    if (tid < 64) arow[tid] = g_sort[tid];
    __syncthreads();
    int n0 = blockIdx.x * 64;
    int ks = blockIdx.y;
    int tx = tid & 15, ty = tid >> 4;
    int lr = tid >> 2, ls = tid & 3;
    float acc[4][4] = {};
    for (int k0 = ks * 256; k0 < ks * 256 + 256; k0 += 32) {
        const float4* ap = (const float4*)(enc + (size_t)arow[lr] * ENCD + k0);
        stash_tile(As, lr, ls, ap[ls], ap[ls + 4]);
        const float4* bp = (const float4*)(Wsel + (size_t)(n0 + lr) * ENCD + k0);
        stash_tile(Bs, lr, ls, bp[ls], bp[ls + 4]);
        __syncthreads();
        mm_inner(As, Bs, acc, tx, ty);
        __syncthreads();
    }
    float* outp = g_ip[blockIdx.z * 8 + ks];
#pragma unroll
    for (int i = 0; i < 4; i++) {
        int m = ty*4 + i;
#pragma unroll
        for (int j = 0; j < 4; j++)
            outp[m * HD + n0 + tx*4 + j] = acc[i][j];
    }
}

__global__ void k_init_red(const float* __restrict__ bh, const float* __restrict__ bc) {
    int idx = blockIdx.x * 256 + threadIdx.x;     // 256 blocks -> 65536 = 2 * NB*HD
    int z = idx >> 15, r = idx & 32767;
    int n = r & 511;
    float s = 0.f;
#pragma unroll
    for (int p = 0; p < 8; p++) s += g_ip[z * 8 + p][r];
    if (z == 0) g_h[r] = s + bh[n];
    else        g_c[r] = s + bc[n];
}

// ---------------- shared mma.sync mainloop (128x128 tile, 3-term bf16) ----------------
__device__ __forceinline__ void tile_load(uint32_t st,
        const __nv_bfloat16* Ahi, const __nv_bfloat16* Alo,
        const __nv_bfloat16* Bhi, const __nv_bfloat16* Blo,
        int mtile, int ntile, int c, int tid) {
    const char* s0 = (const char*)(Ahi + ((size_t)mtile * KC + c) * 8192);
    const char* s1 = (const char*)(Alo + ((size_t)mtile * KC + c) * 8192);
    const char* s2 = (const char*)(Bhi + ((size_t)ntile * KC + c) * 8192);
    const char* s3 = (const char*)(Blo + ((size_t)ntile * KC + c) * 8192);
#pragma unroll
    for (int i = tid * 16; i < 16384; i += 4096) {
        cp16(st + i,         s0 + i);
        cp16(st + 16384 + i, s1 + i);
        cp16(st + 32768 + i, s2 + i);
        cp16(st + 49152 + i, s3 + i);
    }
    asm volatile("cp.async.commit_group;" ::: "memory");
}

__device__ __forceinline__ void mma_mainloop(uint32_t sb, int tid,
        const __nv_bfloat16* Ahi, const __nv_bfloat16* Alo,
        const __nv_bfloat16* Bhi, const __nv_bfloat16* Blo,
        int mtile, int ntile, bool act0, bool act1, float acc[2][8][4]) {
    int lane = tid & 31, warp = tid >> 5;
    int m0 = (warp & 3) * 32, n0w = (warp >> 2) * 64;
    int rl = lane & 7, q = lane >> 3;
    bool mact[2] = {act0, act1};
    tile_load(sb, Ahi, Alo, Bhi, Blo, mtile, ntile, 0, tid);
    for (int c = 0; c < KC; c++) {
        asm volatile("cp.async.wait_group 0;" ::: "memory");
        __syncthreads();
        if (c + 1 < KC)
            tile_load(sb + (uint32_t)((c + 1) & 1) * 65536, Ahi, Alo, Bhi, Blo,
                      mtile, ntile, c + 1, tid);
        uint32_t stA  = sb + (uint32_t)(c & 1) * 65536;
        uint32_t stAl = stA + 16384, stB = stA + 32768, stBl = stA + 49152;
#pragma unroll
        for (int s = 0; s < 4; s++) {
            uint32_t bh[8][2], bl[8][2];
#pragma unroll
            for (int g = 0; g < 4; g++) {
                int row = n0w + g * 16 + ((q >> 1) << 3) + rl;
                int off = row * 128 + s * 32 + ((q & 1) << 4);
                int sw = off ^ ((off >> 3) & 0x70);
                uint32_t r0, r1, r2, r3;
                LDSM4(r0, r1, r2, r3, stB + sw);
                bh[g*2][0] = r0; bh[g*2][1] = r1; bh[g*2+1][0] = r2; bh[g*2+1][1] = r3;
                LDSM4(r0, r1, r2, r3, stBl + sw);
                bl[g*2][0] = r0; bl[g*2][1] = r1; bl[g*2+1][0] = r2; bl[g*2+1][1] = r3;
            }
#pragma unroll
            for (int f = 0; f < 2; f++) {
                if (!mact[f]) continue;
                int row = m0 + f * 16 + rl + ((q & 1) << 3);
                int off = row * 128 + s * 32 + ((q >> 1) << 4);
                int sw = off ^ ((off >> 3) & 0x70);
                uint32_t ah[4], al[4];
                LDSM4(ah[0], ah[1], ah[2], ah[3], stA + sw);
                LDSM4(al[0], al[1], al[2], al[3], stAl + sw);
#pragma unroll
                for (int nf = 0; nf < 8; nf++) {
                    MMA16816(acc[f][nf], ah, bh[nf]);
                    MMA16816(acc[f][nf], ah, bl[nf]);
                    MMA16816(acc[f][nf], al, bh[nf]);
                }
            }
        }
        __syncthreads();
    }
}

// ---------------- XW on mma.sync: g_XW = embs @ w_ih^T + b_ih ----------------
__global__ void __launch_bounds__(256, 1)
k_xw_mma(const float* __restrict__ bih) {
    extern __shared__ char smem[];
    uint32_t sb = s2u(smem);
    int tid = threadIdx.x;
    int lane = tid & 31, warp = tid >> 5;
    int m0 = (warp & 3) * 32, n0w = (warp >> 2) * 64;
    int mtile = blockIdx.x % MT, ntile = blockIdx.x / MT;

    float acc[2][8][4];
#pragma unroll
    for (int f = 0; f < 2; f++)
#pragma unroll
        for (int nf = 0; nf < 8; nf++)
#pragma unroll
            for (int e = 0; e < 4; e++) acc[f][nf][e] = 0.f;

    mma_mainloop(sb, tid, g_Ehi, g_Elo, g_Whi, g_Wlo, mtile, ntile, true, true, acc);

#pragma unroll
    for (int f = 0; f < 2; f++) {
        int rbase = mtile * 128 + m0 + f * 16 + (lane >> 2);
#pragma unroll
        for (int rr = 0; rr < 2; rr++) {
            int r = rbase + rr * 8;
            float* orow = g_XW + (size_t)r * GD;
#pragma unroll
            for (int nf = 0; nf < 8; nf++) {
                int n = ntile * 128 + n0w + nf * 8 + ((lane & 3) << 1);
                float2 bb = __ldg((const float2*)&bih[n]);
                float2 v;
                v.x = acc[f][nf][rr * 2 + 0] + bb.x;
                v.y = acc[f][nf][rr * 2 + 1] + bb.y;
                *(float2*)&orow[n] = v;
            }
        }
    }
}

// ---------------- persistent recurrence: 50 steps in one launch ----------------
__device__ __forceinline__ void gsync(unsigned target) {
    __syncthreads();
    if (threadIdx.x == 0) {
        __threadfence();
        unsigned old = atomicAdd(&g_cnt, 1);
        if (old == RB - 1) {
            atomicExch(&g_cnt, 0);
            __threadfence();
            atomicAdd(&g_phase, 1);
        } else {
            while ((int)(*(volatile unsigned*)&g_phase - target) < 0) {}
        }
    }
    __syncthreads();
}

__global__ void __launch_bounds__(256, 1) k_rnn(const float* __restrict__ whh,
                                                const float* __restrict__ bhh) {
    extern __shared__ float sm[];
    float* w_s = sm;               // [k][16]
    float* h_s = sm + 512 * 16;    // [b][516]
    int tid = threadIdx.x, bi = blockIdx.x;
    int n0 = bi * 16;
    for (int idx = tid; idx < 16 * 512; idx += 256) {
        int r = idx >> 9, k = idx & 511;
        w_s[k * 16 + r] = whh[(size_t)(n0 + r) * HD + k];
    }
    int gb = tid >> 2, gn = (tid & 3) * 4;
    int pb = tid >> 2, pj = bi * 4 + (tid & 3);
    float c_reg = g_c[pb * HD + pj];
    float4 bh4 = *(const float4*)&bhh[n0 + gn];
    unsigned base = *(volatile unsigned*)&g_phase;
    unsigned lp = 0;
    __syncthreads();
    for (int t = 0; t < NT; t++) {
        for (int idx = tid; idx < (NB * HD) / 4; idx += 256) {
            int lin = idx * 4;
            int b = lin >> 9, k = lin & 511;
            float4 hv = __ldcg((const float4*)&g_h[b * HD + k]);
            *(float4*)&h_s[b * 516 + k] = hv;
        }
        __syncthreads();
        float a0 = 0.f, a1 = 0.f, a2 = 0.f, a3 = 0.f;
        const float* hrow = &h_s[gb * 516];
#pragma unroll 8
        for (int k = 0; k < 512; k++) {
            float h = hrow[k];
            float4 w = *(const float4*)&w_s[k * 16 + gn];
            a0 += h * w.x; a1 += h * w.y; a2 += h * w.z; a3 += h * w.w;
        }
        float4 xv = __ldg((const float4*)&g_XW[((size_t)t * NB + gb) * GD + n0 + gn]);
        float4 gv = make_float4(a0 + xv.x + bh4.x, a1 + xv.y + bh4.y,
                                a2 + xv.z + bh4.z, a3 + xv.w + bh4.w);
        __stcg((float4*)&g_gates[gb * GD + n0 + gn], gv);
        gsync(base + (++lp));
        float gi = __ldcg(&g_gates[pb * GD + pj]);
        float gf = __ldcg(&g_gates[pb * GD + 512 + pj]);
        float gg = __ldcg(&g_gates[pb * GD + 1024 + pj]);
        float go = __ldcg(&g_gates[pb * GD + 1536 + pj]);
        float si = 1.f / (1.f + expf(-gi));
        float sf = 1.f / (1.f + expf(-gf));
        float so = 1.f / (1.f + expf(-go));
        c_reg = sf * c_reg + si * tanhf(gg);
        float hv = so * tanhf(c_reg);
        __stcg(&g_h[pb * HD + pj], hv);
        __stcg(&g_H[((size_t)t * NB + pb) * HD + pj], hv);
        gsync(base + (++lp));
        __syncthreads();
    }
}

// ---------------- FC on mma.sync: preds = H @ w_fc^T + b_fc, masked ----------------
__global__ void __launch_bounds__(256, 1)
k_fc_mma(const float* __restrict__ bfc, float* __restrict__ out) {
    extern __shared__ char smem[];
    uint32_t sb = s2u(smem);
    int tid = threadIdx.x;
    int lane = tid & 31, warp = tid >> 5;
    int m0 = (warp & 3) * 32, n0w = (warp >> 2) * 64;
    int mtile = blockIdx.x % MT, ntile = blockIdx.x / MT;

    int g0 = mtile * 128 + m0;
    int t_f = g0 >> 6, b_f = g0 & 63;
    bool act0 = (__ldg(&g_dlen[b_f]) > t_f);
    bool act1 = (__ldg(&g_dlen[b_f + 16]) > t_f);

    float acc[2][8][4];
#pragma unroll
    for (int f = 0; f < 2; f++)
#pragma unroll
        for (int nf = 0; nf < 8; nf++)
#pragma unroll
            for (int e = 0; e < 4; e++) acc[f][nf][e] = 0.f;

    mma_mainloop(sb, tid, g_Ahi, g_Alo, g_Bhi, g_Blo, mtile, ntile, act0, act1, acc);

#pragma unroll
    for (int f = 0; f < 2; f++) {
        int rbase = mtile * 128 + m0 + f * 16 + (lane >> 2);
#pragma unroll
        for (int rr = 0; rr < 2; rr++) {
            int r = rbase + rr * 8;
            int t = r >> 6, b = r & 63;
            bool act = (__ldg(&g_dlen[b]) > t);
            float* orow = out + ((size_t)b * NT + t) * VD;
#pragma unroll
            for (int nf = 0; nf < 8; nf++) {
                int n = ntile * 128 + n0w + nf * 8 + ((lane & 3) << 1);
                if (n < VD) {
                    float2 v;
                    if (act) {
                        float2 bb = __ldg((const float2*)&bfc[n]);
                        v.x = acc[f][nf][rr * 2 + 0] + bb.x;
                        v.y = acc[f][nf][rr * 2 + 1] + bb.y;
                    } else { v.x = 0.f; v.y = 0.f; }
                    *(float2*)&orow[n] = v;
                }
            }
        }
    }
}

// ---------------- launch ----------------
extern "C" void kernel_launch(void* const* d_in, const int* in_sizes, int n_in,
                              void* d_out, int out_size) {
    const float* enc      = (const float*)d_in[0];
    const int*   caps     = (const int*)  d_in[1];
    const int*   clen     = (const int*)  d_in[2];
    const float* emb      = (const float*)d_in[3];
    const float* w_ih     = (const float*)d_in[4];
    const float* b_ih     = (const float*)d_in[5];
    const float* w_hh     = (const float*)d_in[6];
    const float* b_hh     = (const float*)d_in[7];
    const float* w_init_h = (const float*)d_in[8];
    const float* b_init_h = (const float*)d_in[9];
    const float* w_init_c = (const float*)d_in[10];
    const float* b_init_c = (const float*)d_in[11];
    const float* w_fc     = (const float*)d_in[12];
    const float* b_fc     = (const float*)d_in[13];
    float* out = (float*)d_out;

    const long long pred_elems = (long long)NB * NT * VD;
    int extras = ((long long)out_size > pred_elems) ? 1 : 0;

    const int rnn_smem = (512 * 16 + 64 * 516) * 4;   // 164864
    const int fc_smem  = 2 * 65536;                   // 131072
    cudaFuncSetAttribute(k_rnn,    cudaFuncAttributeMaxDynamicSharedMemorySize, rnn_smem);
    cudaFuncSetAttribute(k_fc_mma, cudaFuncAttributeMaxDynamicSharedMemorySize, fc_smem);
    cudaFuncSetAttribute(k_xw_mma, cudaFuncAttributeMaxDynamicSharedMemorySize, fc_smem);

    k_sort<<<1, 256>>>(clen, caps, out + pred_elems, extras);
    k_packB<<<dim3(NTB, KC), 256>>>(w_fc);
    k_packW<<<dim3(NTW, KC), 256>>>(w_ih);
    k_packE<<<dim3(MT, KC), 256>>>(emb, caps);
    k_init_part<<<dim3(HD / 64, 8, 2), 256>>>(enc, w_init_h, w_init_c);
    k_init_red<<<256, 256>>>(b_init_h, b_init_c);
    k_xw_mma<<<MT * NTW, 256, fc_smem>>>(b_ih);
    k_rnn<<<RB, 256, rnn_smem>>>(w_hh, b_hh);
    k_packA<<<dim3(MT, KC), 256>>>();
    k_fc_mma<<<MT * NTB, 256, fc_smem>>>(b_fc, out);
}

// round 12
// speedup vs baseline: 2.2903x; 1.2330x over previous
#include <cuda_runtime.h>
#include <cuda_bf16.h>
#include <math.h>
#include <stdint.h>

#define NB   64
#define CL   51
#define NT   50
#define ED   512
#define HD   512
#define VD   30000
#define ENCD 2048
#define GD   2048

#define MT   25      // max M tiles (128 rows)
#define NTB  235     // FC N tiles (128 vocab rows) -> 30080 padded
#define NTW  16      // XW N tiles (2048 / 128)
#define KC   8       // K chunks of 64
#define RB   128     // persistent rnn blocks

// ---------------- device scratch ----------------
__device__ int      g_sort[NB];
__device__ int      g_dlen[NB];
__device__ int      g_cum[NB + 1];
__device__ int      g_Atot;
__device__ float    g_hbuf[2][NB * HD];
__device__ float    g_c[NB * HD];
__device__ float    g_XW[(size_t)NT * NB * GD];
__device__ float    g_ip[16][NB * HD];
__device__ unsigned g_cnt;
__device__ unsigned g_phase;

// packed bf16 SW128-swizzled tiles: [tile][kc][128 rows x 64 k] = 8192 bf16 (16KB)
__device__ __align__(128) __nv_bfloat16 g_Bhi[(size_t)NTB * KC * 8192];
__device__ __align__(128) __nv_bfloat16 g_Blo[(size_t)NTB * KC * 8192];
__device__ __align__(128) __nv_bfloat16 g_Ahi[(size_t)MT  * KC * 8192];   // compacted active rows; padding stays 0
__device__ __align__(128) __nv_bfloat16 g_Alo[(size_t)MT  * KC * 8192];
__device__ __align__(128) __nv_bfloat16 g_Whi[(size_t)NTW * KC * 8192];
__device__ __align__(128) __nv_bfloat16 g_Wlo[(size_t)NTW * KC * 8192];
__device__ __align__(128) __nv_bfloat16 g_Ehi[(size_t)MT  * KC * 8192];
__device__ __align__(128) __nv_bfloat16 g_Elo[(size_t)MT  * KC * 8192];

// ---------------- PTX helpers (baseline sm_80-level only) ----------------
__device__ __forceinline__ uint32_t s2u(const void* p) {
    uint32_t a;
    asm("{ .reg .u64 t; cvta.to.shared.u64 t, %1; cvt.u32.u64 %0, t; }" : "=r"(a) : "l"(p));
    return a;
}
__device__ __forceinline__ void cp16(uint32_t d, const void* s) {
    asm volatile("cp.async.cg.shared.global [%0], [%1], 16;" :: "r"(d), "l"(s));
}
#define LDSM4(r0, r1, r2, r3, addr) \
    asm volatile("ldmatrix.sync.aligned.m8n8.x4.shared.b16 {%0,%1,%2,%3}, [%4];" \
        : "=r"(r0), "=r"(r1), "=r"(r2), "=r"(r3) : "r"(addr))
#define MMA16816(d, a, b) \
    asm volatile("mma.sync.aligned.m16n8k16.row.col.f32.bf16.bf16.f32 " \
        "{%0,%1,%2,%3},{%4,%5,%6,%7},{%8,%9},{%0,%1,%2,%3};" \
        : "+f"((d)[0]), "+f"((d)[1]), "+f"((d)[2]), "+f"((d)[3]) \
        : "r"((a)[0]), "r"((a)[1]), "r"((a)[2]), "r"((a)[3]), "r"((b)[0]), "r"((b)[1]))

// ---------------- fp32 GEMM tile helpers (init GEMM) ----------------
__device__ __forceinline__ void stash_tile(float (*S)[65], int lr, int ls, float4 v0, float4 v1) {
    S[ls*4+0][lr] = v0.x; S[ls*4+1][lr] = v0.y; S[ls*4+2][lr] = v0.z; S[ls*4+3][lr] = v0.w;
    S[16+ls*4+0][lr] = v1.x; S[16+ls*4+1][lr] = v1.y; S[16+ls*4+2][lr] = v1.z; S[16+ls*4+3][lr] = v1.w;
}
__device__ __forceinline__ void mm_inner(float (*As)[65], float (*Bs)[65],
                                         float acc[4][4], int tx, int ty) {
#pragma unroll
    for (int kk = 0; kk < 32; kk++) {
        float a0 = As[kk][ty*4+0], a1 = As[kk][ty*4+1];
        float a2 = As[kk][ty*4+2], a3 = As[kk][ty*4+3];
        float b0 = Bs[kk][tx*4+0], b1 = Bs[kk][tx*4+1];
        float b2 = Bs[kk][tx*4+2], b3 = Bs[kk][tx*4+3];
        acc[0][0] += a0*b0; acc[0][1] += a0*b1; acc[0][2] += a0*b2; acc[0][3] += a0*b3;
        acc[1][0] += a1*b0; acc[1][1] += a1*b1; acc[1][2] += a1*b2; acc[1][3] += a1*b3;
        acc[2][0] += a2*b0; acc[2][1] += a2*b1; acc[2][2] += a2*b2; acc[2][3] += a2*b3;
        acc[3][0] += a3*b0; acc[3][1] += a3*b1; acc[3][2] += a3*b2; acc[3][3] += a3*b3;
    }
}

// ---------------- sort + cum + extras ----------------
__global__ void k_sort(const int* __restrict__ lens, const int* __restrict__ caps,
                       float* __restrict__ out_extra, int extras) {
    __shared__ int slen[NB];
    __shared__ int sidx[NB];
    int t = threadIdx.x;
    if (t < NB) slen[t] = lens[t];
    __syncthreads();
    if (t < NB) {
        int Li = slen[t];
        int r = 0;
        for (int j = 0; j < NB; j++) {
            int Lj = slen[j];
            if (Lj > Li || (Lj == Li && j < t)) r++;
        }
        sidx[r] = t;
    }
    __syncthreads();
    if (t < NB) { g_sort[t] = sidx[t]; g_dlen[t] = slen[sidx[t]] - 1; }
    __syncthreads();
    if (t == 0) {
        int s = 0;
        for (int b = 0; b < NB; b++) { g_cum[b] = s; s += slen[sidx[b]] - 1; }
        g_cum[NB] = s;
        g_Atot = s;
    }
    if (extras) {
        for (int i = t; i < NB * CL; i += blockDim.x) {
            int b = i / CL, j = i % CL;
            out_extra[i] = (float)caps[sidx[b] * CL + j];
        }
        if (t < NB) out_extra[NB*CL + t]      = (float)(slen[sidx[t]] - 1);
        if (t < NB) out_extra[NB*CL + NB + t] = (float)sidx[t];
    }
}

// ---------------- zero inactive output rows ----------------
__global__ void k_zero(float* __restrict__ out) {
    int b = blockIdx.x / NT, t = blockIdx.x % NT;
    if (t < g_dlen[b]) return;
    float4 z = make_float4(0.f, 0.f, 0.f, 0.f);
    float* row = out + ((size_t)b * NT + t) * VD;
    for (int i = threadIdx.x * 4; i < VD; i += 256 * 4)
        *(float4*)&row[i] = z;
}

// ---------------- packers: fp32 -> swizzled bf16 hi/lo (128-row x 64-k tiles) ----------------
__global__ void k_packB(const float* __restrict__ wfc) {
    int tile = blockIdx.x, kc = blockIdx.y;
    size_t base = ((size_t)tile * KC + kc) * 8192;
    for (int i = threadIdx.x; i < 8192; i += 256) {
        int r = i >> 6, c = i & 63;
        int n = tile * 128 + r;
        float v = (n < VD) ? wfc[(size_t)n * HD + kc * 64 + c] : 0.f;
        __nv_bfloat16 hi = __float2bfloat16(v);
        __nv_bfloat16 lo = __float2bfloat16(v - __bfloat162float(hi));
        uint32_t off = (uint32_t)r * 128 + c * 2;
        uint32_t sw = off ^ ((off >> 3) & 0x70);
        g_Bhi[base + (sw >> 1)] = hi;
        g_Blo[base + (sw >> 1)] = lo;
    }
}

__global__ void k_packW(const float* __restrict__ wih) {
    int tile = blockIdx.x, kc = blockIdx.y;
    size_t base = ((size_t)tile * KC + kc) * 8192;
    for (int i = threadIdx.x; i < 8192; i += 256) {
        int r = i >> 6, c = i & 63;
        int n = tile * 128 + r;
        float v = wih[(size_t)n * ED + kc * 64 + c];
        __nv_bfloat16 hi = __float2bfloat16(v);
        __nv_bfloat16 lo = __float2bfloat16(v - __bfloat162float(hi));
        uint32_t off = (uint32_t)r * 128 + c * 2;
        uint32_t sw = off ^ ((off >> 3) & 0x70);
        g_Whi[base + (sw >> 1)] = hi;
        g_Wlo[base + (sw >> 1)] = lo;
    }
}

// gathered sorted embedding rows (t-major rows; after k_sort)
__global__ void k_packE(const float* __restrict__ emb, const int* __restrict__ caps) {
    int tile = blockIdx.x, kc = blockIdx.y;
    __shared__ int tok[128];
    size_t base = ((size_t)tile * KC + kc) * 8192;
    if (threadIdx.x < 128) {
        int r = threadIdx.x;
        int t = tile * 2 + (r >> 6), b = r & 63;
        tok[r] = caps[g_sort[b] * CL + t];
    }
    __syncthreads();
    for (int i = threadIdx.x; i < 8192; i += 256) {
        int r = i >> 6, c = i & 63;
        float v = emb[(size_t)tok[r] * ED + kc * 64 + c];
        __nv_bfloat16 hi = __float2bfloat16(v);
        __nv_bfloat16 lo = __float2bfloat16(v - __bfloat162float(hi));
        uint32_t off = (uint32_t)r * 128 + c * 2;
        uint32_t sw = off ^ ((off >> 3) & 0x70);
        g_Ehi[base + (sw >> 1)] = hi;
        g_Elo[base + (sw >> 1)] = lo;
    }
}

// ---------------- init h0/c0: K-split partials + fused reduce ----------------
__global__ void k_init_part(const float* __restrict__ enc,
                            const float* __restrict__ wh, const float* __restrict__ wc) {
    __shared__ float As[32][65], Bs[32][65];
    __shared__ int arow[64];
    const float* Wsel = blockIdx.z ? wc : wh;
    int tid = threadIdx.x;
    if (tid < 64) arow[tid] = g_sort[tid];
    __syncthreads();
    int n0 = blockIdx.x * 64;
    int ks = blockIdx.y;
    int tx = tid & 15, ty = tid >> 4;
    int lr = tid >> 2, ls = tid & 3;
    float acc[4][4] = {};
    for (int k0 = ks * 256; k0 < ks * 256 + 256; k0 += 32) {
        const float4* ap = (const float4*)(enc + (size_t)arow[lr] * ENCD + k0);
        stash_tile(As, lr, ls, ap[ls], ap[ls + 4]);
        const float4* bp = (const float4*)(Wsel + (size_t)(n0 + lr) * ENCD + k0);
        stash_tile(Bs, lr, ls, bp[ls], bp[ls + 4]);
        __syncthreads();
        mm_inner(As, Bs, acc, tx, ty);
        __syncthreads();
    }
    float* outp = g_ip[blockIdx.z * 8 + ks];
#pragma unroll
    for (int i = 0; i < 4; i++) {
        int m = ty*4 + i;
#pragma unroll
        for (int j = 0; j < 4; j++)
            outp[m * HD + n0 + tx*4 + j] = acc[i][j];
    }
}

__global__ void k_init_red(const float* __restrict__ bh, const float* __restrict__ bc) {
    int idx = blockIdx.x * 256 + threadIdx.x;
    int z = idx >> 15, r = idx & 32767;
    int n = r & 511;
    float s = 0.f;
#pragma unroll
    for (int p = 0; p < 8; p++) s += g_ip[z * 8 + p][r];
    if (z == 0) g_hbuf[0][r] = s + bh[n];
    else        g_c[r] = s + bc[n];
}

// ---------------- shared mma.sync mainloop (128x128 tile, 3-term bf16) ----------------
__device__ __forceinline__ void tile_load(uint32_t st,
        const __nv_bfloat16* Ahi, const __nv_bfloat16* Alo,
        const __nv_bfloat16* Bhi, const __nv_bfloat16* Blo,
        int mtile, int ntile, int c, int tid) {
    const char* s0 = (const char*)(Ahi + ((size_t)mtile * KC + c) * 8192);
    const char* s1 = (const char*)(Alo + ((size_t)mtile * KC + c) * 8192);
    const char* s2 = (const char*)(Bhi + ((size_t)ntile * KC + c) * 8192);
    const char* s3 = (const char*)(Blo + ((size_t)ntile * KC + c) * 8192);
#pragma unroll
    for (int i = tid * 16; i < 16384; i += 4096) {
        cp16(st + i,         s0 + i);
        cp16(st + 16384 + i, s1 + i);
        cp16(st + 32768 + i, s2 + i);
        cp16(st + 49152 + i, s3 + i);
    }
    asm volatile("cp.async.commit_group;" ::: "memory");
}

__device__ __forceinline__ void mma_mainloop(uint32_t sb, int tid,
        const __nv_bfloat16* Ahi, const __nv_bfloat16* Alo,
        const __nv_bfloat16* Bhi, const __nv_bfloat16* Blo,
        int mtile, int ntile, bool act0, bool act1, float acc[2][8][4]) {
    int lane = tid & 31, warp = tid >> 5;
    int m0 = (warp & 3) * 32, n0w = (warp >> 2) * 64;
    int rl = lane & 7, q = lane >> 3;
    bool mact[2] = {act0, act1};
    tile_load(sb, Ahi, Alo, Bhi, Blo, mtile, ntile, 0, tid);
    for (int c = 0; c < KC; c++) {
        asm volatile("cp.async.wait_group 0;" ::: "memory");
        __syncthreads();
        if (c + 1 < KC)
            tile_load(sb + (uint32_t)((c + 1) & 1) * 65536, Ahi, Alo, Bhi, Blo,
                      mtile, ntile, c + 1, tid);
        uint32_t stA  = sb + (uint32_t)(c & 1) * 65536;
        uint32_t stAl = stA + 16384, stB = stA + 32768, stBl = stA + 49152;
#pragma unroll
        for (int s = 0; s < 4; s++) {
            uint32_t bh[8][2], bl[8][2];
#pragma unroll
            for (int g = 0; g < 4; g++) {
                int row = n0w + g * 16 + ((q >> 1) << 3) + rl;
                int off = row * 128 + s * 32 + ((q & 1) << 4);
                int sw = off ^ ((off >> 3) & 0x70);
                uint32_t r0, r1, r2, r3;
                LDSM4(r0, r1, r2, r3, stB + sw);
                bh[g*2][0] = r0; bh[g*2][1] = r1; bh[g*2+1][0] = r2; bh[g*2+1][1] = r3;
                LDSM4(r0, r1, r2, r3, stBl + sw);
                bl[g*2][0] = r0; bl[g*2][1] = r1; bl[g*2+1][0] = r2; bl[g*2+1][1] = r3;
            }
#pragma unroll
            for (int f = 0; f < 2; f++) {
                if (!mact[f]) continue;
                int row = m0 + f * 16 + rl + ((q & 1) << 3);
                int off = row * 128 + s * 32 + ((q >> 1) << 4);
                int sw = off ^ ((off >> 3) & 0x70);
                uint32_t ah[4], al[4];
                LDSM4(ah[0], ah[1], ah[2], ah[3], stA + sw);
                LDSM4(al[0], al[1], al[2], al[3], stAl + sw);
#pragma unroll
                for (int nf = 0; nf < 8; nf++) {
                    MMA16816(acc[f][nf], ah, bh[nf]);
                    MMA16816(acc[f][nf], ah, bl[nf]);
                    MMA16816(acc[f][nf], al, bh[nf]);
                }
            }
        }
        __syncthreads();
    }
}

// ---------------- XW on mma.sync: g_XW = embs @ w_ih^T + b_ih ----------------
__global__ void __launch_bounds__(256, 1)
k_xw_mma(const float* __restrict__ bih) {
    extern __shared__ char smem[];
    uint32_t sb = s2u(smem);
    int tid = threadIdx.x;
    int lane = tid & 31, warp = tid >> 5;
    int m0 = (warp & 3) * 32, n0w = (warp >> 2) * 64;
    int mtile = blockIdx.x % MT, ntile = blockIdx.x / MT;

    float acc[2][8][4];
#pragma unroll
    for (int f = 0; f < 2; f++)
#pragma unroll
        for (int nf = 0; nf < 8; nf++)
#pragma unroll
            for (int e = 0; e < 4; e++) acc[f][nf][e] = 0.f;

    mma_mainloop(sb, tid, g_Ehi, g_Elo, g_Whi, g_Wlo, mtile, ntile, true, true, acc);

#pragma unroll
    for (int f = 0; f < 2; f++) {
        int rbase = mtile * 128 + m0 + f * 16 + (lane >> 2);
#pragma unroll
        for (int rr = 0; rr < 2; rr++) {
            int r = rbase + rr * 8;
            float* orow = g_XW + (size_t)r * GD;
#pragma unroll
            for (int nf = 0; nf < 8; nf++) {
                int n = ntile * 128 + n0w + nf * 8 + ((lane & 3) << 1);
                float2 bb = __ldg((const float2*)&bih[n]);
                float2 v;
                v.x = acc[f][nf][rr * 2 + 0] + bb.x;
                v.y = acc[f][nf][rr * 2 + 1] + bb.y;
                *(float2*)&orow[n] = v;
            }
        }
    }
}

// ---------------- persistent recurrence: 1 global barrier per step, fused pack ----------------
__device__ __forceinline__ void gsync(unsigned target) {
    __syncthreads();
    if (threadIdx.x == 0) {
        __threadfence();
        unsigned old = atomicAdd(&g_cnt, 1);
        if (old == RB - 1) {
            atomicExch(&g_cnt, 0);
            __threadfence();
            atomicAdd(&g_phase, 1);
        } else {
            while ((int)(*(volatile unsigned*)&g_phase - target) < 0) {}
        }
    }
    __syncthreads();
}

// block bi owns output columns j in [bi*4, bi*4+4) across ALL four gates.
__global__ void __launch_bounds__(256, 1) k_rnn(const float* __restrict__ whh,
                                                const float* __restrict__ bhh) {
    extern __shared__ float sm[];
    float* w_s = sm;                       // [k=512][16]  (idx = gate*4 + q)
    float* h_s = sm + 512 * 16;            // [b=64][516]
    float* s_g = sm + 512 * 16 + 64 * 516; // [b=64][16]
    int tid = threadIdx.x, bi = blockIdx.x;
    int j0 = bi * 4;
    for (int i = tid; i < 16 * 512; i += 256) {
        int idx = i >> 9, k = i & 511;
        int n = (idx >> 2) * 512 + j0 + (idx & 3);   // gate=(idx>>2), q=(idx&3)
        w_s[k * 16 + idx] = whh[(size_t)n * HD + k];
    }
    int gb = tid >> 2, gn = tid & 3;       // gemm: batch gb, gate gn (4 q's)
    int pb = gb, q = gn;                   // pointwise: batch pb, column q
    float c_reg = g_c[pb * HD + j0 + q];
    int dl = __ldg(&g_dlen[pb]);
    int cumb = __ldg(&g_cum[pb]);
    float4 b4 = *(const float4*)&bhh[gn * 512 + j0];
    unsigned base = *(volatile unsigned*)&g_phase;
    unsigned lp = 0;
    __syncthreads();
    for (int t = 0; t < NT; t++) {
        const float* hsrc = g_hbuf[t & 1];
        for (int idx = tid; idx < (NB * HD) / 4; idx += 256) {
            int lin = idx * 4;
            int b = lin >> 9, k = lin & 511;
            float4 hv = __ldcg((const float4*)&hsrc[b * HD + k]);
            *(float4*)&h_s[b * 516 + k] = hv;
        }
        __syncthreads();
        float a0 = 0.f, a1 = 0.f, a2 = 0.f, a3 = 0.f;
        const float* hrow = &h_s[gb * 516];
#pragma unroll 8
        for (int k = 0; k < 512; k++) {
            float h = hrow[k];
            float4 w = *(const float4*)&w_s[k * 16 + gn * 4];
            a0 += h * w.x; a1 += h * w.y; a2 += h * w.z; a3 += h * w.w;
        }
        float4 xv = __ldg((const float4*)&g_XW[((size_t)t * NB + gb) * GD + gn * 512 + j0]);
        *(float4*)&s_g[gb * 16 + gn * 4] =
            make_float4(a0 + xv.x + b4.x, a1 + xv.y + b4.y,
                        a2 + xv.z + b4.z, a3 + xv.w + b4.w);
        __syncthreads();
        float gi = s_g[pb * 16 + 0  + q];
        float gf = s_g[pb * 16 + 4  + q];
        float gg = s_g[pb * 16 + 8  + q];
        float go = s_g[pb * 16 + 12 + q];
        float si = 1.f / (1.f + expf(-gi));
        float sf = 1.f / (1.f + expf(-gf));
        float so = 1.f / (1.f + expf(-go));
        c_reg = sf * c_reg + si * tanhf(gg);
        float hv = so * tanhf(c_reg);
        __stcg(&g_hbuf[(t + 1) & 1][pb * HD + j0 + q], hv);
        if (t < dl) {   // fused pack into compacted bf16 A-tiles
            int cr = cumb + t;
            int tile = cr >> 7, r = cr & 127;
            int j = j0 + q, kc = j >> 6, cc = j & 63;
            uint32_t off = (uint32_t)r * 128 + cc * 2;
            uint32_t sw = off ^ ((off >> 3) & 0x70);
            size_t pbase = ((size_t)tile * KC + kc) * 8192 + (sw >> 1);
            __nv_bfloat16 hi = __float2bfloat16(hv);
            __nv_bfloat16 lo = __float2bfloat16(hv - __bfloat162float(hi));
            g_Ahi[pbase] = hi;
            g_Alo[pbase] = lo;
        }
        gsync(base + (++lp));
    }
}

// ---------------- FC on mma.sync over compacted rows ----------------
__global__ void __launch_bounds__(256, 1)
k_fc_mma(const float* __restrict__ bfc, float* __restrict__ out) {
    extern __shared__ char smem[];
    __shared__ int cum_s[65];
    uint32_t sb = s2u(smem);
    int tid = threadIdx.x;
    int lane = tid & 31, warp = tid >> 5;
    int m0 = (warp & 3) * 32, n0w = (warp >> 2) * 64;
    int mtile = blockIdx.x % MT, ntile = blockIdx.x / MT;

    int Atot = __ldg(&g_Atot);
    if (mtile * 128 >= Atot) return;
    if (tid < 65) cum_s[tid] = g_cum[tid];

    bool act0 = (mtile * 128 + m0) < Atot;
    bool act1 = (mtile * 128 + m0 + 16) < Atot;

    float acc[2][8][4];
#pragma unroll
    for (int f = 0; f < 2; f++)
#pragma unroll
        for (int nf = 0; nf < 8; nf++)
#pragma unroll
            for (int e = 0; e < 4; e++) acc[f][nf][e] = 0.f;

    mma_mainloop(sb, tid, g_Ahi, g_Alo, g_Bhi, g_Blo, mtile, ntile, act0, act1, acc);

#pragma unroll
    for (int f = 0; f < 2; f++) {
        int rbase = mtile * 128 + m0 + f * 16 + (lane >> 2);
#pragma unroll
        for (int rr = 0; rr < 2; rr++) {
            int r = rbase + rr * 8;
            if (r >= Atot) continue;
            int lo = 0, hi = 63;
            while (lo < hi) {                 // largest b with cum_s[b] <= r
                int mid = (lo + hi + 1) >> 1;
                if (cum_s[mid] <= r) lo = mid; else hi = mid - 1;
            }
            int b = lo, t = r - cum_s[lo];
            float* orow = out + ((size_t)b * NT + t) * VD;
#pragma unroll
            for (int nf = 0; nf < 8; nf++) {
                int n = ntile * 128 + n0w + nf * 8 + ((lane & 3) << 1);
                if (n < VD) {
                    float2 bb = __ldg((const float2*)&bfc[n]);
                    float2 v;
                    v.x = acc[f][nf][rr * 2 + 0] + bb.x;
                    v.y = acc[f][nf][rr * 2 + 1] + bb.y;
                    *(float2*)&orow[n] = v;
                }
            }
        }
    }
}

// ---------------- launch ----------------
extern "C" void kernel_launch(void* const* d_in, const int* in_sizes, int n_in,
                              void* d_out, int out_size) {
    const float* enc      = (const float*)d_in[0];
    const int*   caps     = (const int*)  d_in[1];
    const int*   clen     = (const int*)  d_in[2];
    const float* emb      = (const float*)d_in[3];
    const float* w_ih     = (const float*)d_in[4];
    const float* b_ih     = (const float*)d_in[5];
    const float* w_hh     = (const float*)d_in[6];
    const float* b_hh     = (const float*)d_in[7];
    const float* w_init_h = (const float*)d_in[8];
    const float* b_init_h = (const float*)d_in[9];
    const float* w_init_c = (const float*)d_in[10];
    const float* b_init_c = (const float*)d_in[11];
    const float* w_fc     = (const float*)d_in[12];
    const float* b_fc     = (const float*)d_in[13];
    float* out = (float*)d_out;

    const long long pred_elems = (long long)NB * NT * VD;
    int extras = ((long long)out_size > pred_elems) ? 1 : 0;

    const int rnn_smem = (512 * 16 + 64 * 516 + 64 * 16) * 4;   // 168960
    const int fc_smem  = 2 * 65536;                             // 131072
    cudaFuncSetAttribute(k_rnn,    cudaFuncAttributeMaxDynamicSharedMemorySize, rnn_smem);
    cudaFuncSetAttribute(k_fc_mma, cudaFuncAttributeMaxDynamicSharedMemorySize, fc_smem);
    cudaFuncSetAttribute(k_xw_mma, cudaFuncAttributeMaxDynamicSharedMemorySize, fc_smem);

    k_sort<<<1, 256>>>(clen, caps, out + pred_elems, extras);
    k_zero<<<NB * NT, 256>>>(out);
    k_packB<<<dim3(NTB, KC), 256>>>(w_fc);
    k_packW<<<dim3(NTW, KC), 256>>>(w_ih);
    k_packE<<<dim3(MT, KC), 256>>>(emb, caps);
    k_init_part<<<dim3(HD / 64, 8, 2), 256>>>(enc, w_init_h, w_init_c);
    k_init_red<<<256, 256>>>(b_init_h, b_init_c);
    k_xw_mma<<<MT * NTW, 256, fc_smem>>>(b_ih);
    k_rnn<<<RB, 256, rnn_smem>>>(w_hh, b_hh);
    k_fc_mma<<<MT * NTB, 256, fc_smem>>>(b_fc, out);
}

// round 13
// speedup vs baseline: 2.5246x; 1.1023x over previous
#include <cuda_runtime.h>
#include <cuda_bf16.h>
#include <math.h>
#include <stdint.h>

#define NB   64
#define CL   51
#define NT   50
#define ED   512
#define HD   512
#define VD   30000
#define ENCD 2048
#define GD   2048

#define MT   25      // max M tiles (128 rows)
#define NTB  235     // FC N tiles (128 vocab rows) -> 30080 padded
#define NTW  16      // XW N tiles (2048 / 128)
#define KC   8       // K chunks of 64
#define RB   128     // persistent rnn blocks

// ---------------- device scratch ----------------
__device__ int      g_sort[NB];
__device__ int      g_dlen[NB];
__device__ int      g_cum[NB + 1];
__device__ int      g_Atot;
__device__ float    g_hbuf[2][NB * HD];
__device__ float    g_c[NB * HD];
__device__ float    g_XW[(size_t)NT * NB * GD];
__device__ float    g_ip[16][NB * HD];
__device__ unsigned g_cnt;
__device__ unsigned g_phase;

// packed bf16 SW128-swizzled tiles: [tile][kc][128 rows x 64 k] = 8192 bf16 (16KB)
__device__ __align__(128) __nv_bfloat16 g_Bhi[(size_t)NTB * KC * 8192];
__device__ __align__(128) __nv_bfloat16 g_Blo[(size_t)NTB * KC * 8192];
__device__ __align__(128) __nv_bfloat16 g_Ahi[(size_t)MT  * KC * 8192];   // compacted active rows; padding stays 0
__device__ __align__(128) __nv_bfloat16 g_Alo[(size_t)MT  * KC * 8192];
__device__ __align__(128) __nv_bfloat16 g_Whi[(size_t)NTW * KC * 8192];
__device__ __align__(128) __nv_bfloat16 g_Wlo[(size_t)NTW * KC * 8192];
__device__ __align__(128) __nv_bfloat16 g_Ehi[(size_t)MT  * KC * 8192];
__device__ __align__(128) __nv_bfloat16 g_Elo[(size_t)MT  * KC * 8192];

// ---------------- PTX helpers ----------------
__device__ __forceinline__ uint32_t s2u(const void* p) {
    uint32_t a;
    asm("{ .reg .u64 t; cvta.to.shared.u64 t, %1; cvt.u32.u64 %0, t; }" : "=r"(a) : "l"(p));
    return a;
}
#define LDSM4(r0, r1, r2, r3, addr) \
    asm volatile("ldmatrix.sync.aligned.m8n8.x4.shared.b16 {%0,%1,%2,%3}, [%4];" \
        : "=r"(r0), "=r"(r1), "=r"(r2), "=r"(r3) : "r"(addr))
#define MMA16816(d, a, b) \
    asm volatile("mma.sync.aligned.m16n8k16.row.col.f32.bf16.bf16.f32 " \
        "{%0,%1,%2,%3},{%4,%5,%6,%7},{%8,%9},{%0,%1,%2,%3};" \
        : "+f"((d)[0]), "+f"((d)[1]), "+f"((d)[2]), "+f"((d)[3]) \
        : "r"((a)[0]), "r"((a)[1]), "r"((a)[2]), "r"((a)[3]), "r"((b)[0]), "r"((b)[1]))

__device__ __forceinline__ void mbar_wait(uint32_t mbar, uint32_t parity) {
    asm volatile(
        "{\n\t.reg .pred P;\n\tLW_%=: \n\t"
        "mbarrier.try_wait.parity.shared.b64 P, [%0], %1;\n\t"
        "@P bra LD_%=;\n\tbra LW_%=;\n\tLD_%=: \n\t}"
        :: "r"(mbar), "r"(parity) : "memory");
}
__device__ __forceinline__ void bulk16k(uint32_t dst, const void* src, uint32_t mbar) {
    asm volatile(
        "cp.async.bulk.shared::cta.global.mbarrier::complete_tx::bytes [%0], [%1], %2, [%3];"
        :: "r"(dst), "l"(src), "r"(16384u), "r"(mbar) : "memory");
}
__device__ __forceinline__ void issue_chunk(uint32_t st, uint32_t mbar,
        const __nv_bfloat16* Ahi, const __nv_bfloat16* Alo,
        const __nv_bfloat16* Bhi, const __nv_bfloat16* Blo,
        int mtile, int ntile, int c) {
    asm volatile("mbarrier.arrive.expect_tx.shared.b64 _, [%0], %1;"
                 :: "r"(mbar), "r"(65536u) : "memory");
    bulk16k(st,         Ahi + ((size_t)mtile * KC + c) * 8192, mbar);
    bulk16k(st + 16384, Alo + ((size_t)mtile * KC + c) * 8192, mbar);
    bulk16k(st + 32768, Bhi + ((size_t)ntile * KC + c) * 8192, mbar);
    bulk16k(st + 49152, Blo + ((size_t)ntile * KC + c) * 8192, mbar);
}

// ---------------- fp32 GEMM tile helpers (init GEMM) ----------------
__device__ __forceinline__ void stash_tile(float (*S)[65], int lr, int ls, float4 v0, float4 v1) {
    S[ls*4+0][lr] = v0.x; S[ls*4+1][lr] = v0.y; S[ls*4+2][lr] = v0.z; S[ls*4+3][lr] = v0.w;
    S[16+ls*4+0][lr] = v1.x; S[16+ls*4+1][lr] = v1.y; S[16+ls*4+2][lr] = v1.z; S[16+ls*4+3][lr] = v1.w;
}
__device__ __forceinline__ void mm_inner(float (*As)[65], float (*Bs)[65],
                                         float acc[4][4], int tx, int ty) {
#pragma unroll
    for (int kk = 0; kk < 32; kk++) {
        float a0 = As[kk][ty*4+0], a1 = As[kk][ty*4+1];
        float a2 = As[kk][ty*4+2], a3 = As[kk][ty*4+3];
        float b0 = Bs[kk][tx*4+0], b1 = Bs[kk][tx*4+1];
        float b2 = Bs[kk][tx*4+2], b3 = Bs[kk][tx*4+3];
        acc[0][0] += a0*b0; acc[0][1] += a0*b1; acc[0][2] += a0*b2; acc[0][3] += a0*b3;
        acc[1][0] += a1*b0; acc[1][1] += a1*b1; acc[1][2] += a1*b2; acc[1][3] += a1*b3;
        acc[2][0] += a2*b0; acc[2][1] += a2*b1; acc[2][2] += a2*b2; acc[2][3] += a2*b3;
        acc[3][0] += a3*b0; acc[3][1] += a3*b1; acc[3][2] += a3*b2; acc[3][3] += a3*b3;
    }
}

// ---------------- sort + cum + extras ----------------
__global__ void k_sort(const int* __restrict__ lens, const int* __restrict__ caps,
                       float* __restrict__ out_extra, int extras) {
    __shared__ int slen[NB];
    __shared__ int sidx[NB];
    int t = threadIdx.x;
    if (t < NB) slen[t] = lens[t];
    __syncthreads();
    if (t < NB) {
        int Li = slen[t];
        int r = 0;
        for (int j = 0; j < NB; j++) {
            int Lj = slen[j];
            if (Lj > Li || (Lj == Li && j < t)) r++;
        }
        sidx[r] = t;
    }
    __syncthreads();
    if (t < NB) { g_sort[t] = sidx[t]; g_dlen[t] = slen[sidx[t]] - 1; }
    __syncthreads();
    if (t == 0) {
        int s = 0;
        for (int b = 0; b < NB; b++) { g_cum[b] = s; s += slen[sidx[b]] - 1; }
        g_cum[NB] = s;
        g_Atot = s;
    }
    if (extras) {
        for (int i = t; i < NB * CL; i += blockDim.x) {
            int b = i / CL, j = i % CL;
            out_extra[i] = (float)caps[sidx[b] * CL + j];
        }
        if (t < NB) out_extra[NB*CL + t]      = (float)(slen[sidx[t]] - 1);
        if (t < NB) out_extra[NB*CL + NB + t] = (float)sidx[t];
    }
}

// ---------------- zero inactive output rows ----------------
__global__ void k_zero(float* __restrict__ out) {
    int b = blockIdx.x / NT, t = blockIdx.x % NT;
    if (t < g_dlen[b]) return;
    float4 z = make_float4(0.f, 0.f, 0.f, 0.f);
    float* row = out + ((size_t)b * NT + t) * VD;
    for (int i = threadIdx.x * 4; i < VD; i += 256 * 4)
        *(float4*)&row[i] = z;
}

// ---------------- packers: fp32 -> swizzled bf16 hi/lo, 16B vectorized ----------------
__device__ __forceinline__ void pack8(const float v[8], char* bhi, char* blo, int r, int c8) {
    __align__(16) __nv_bfloat16 hi[8], lo[8];
#pragma unroll
    for (int j = 0; j < 8; j++) {
        hi[j] = __float2bfloat16(v[j]);
        lo[j] = __float2bfloat16(v[j] - __bfloat162float(hi[j]));
    }
    uint32_t off = (uint32_t)r * 128 + c8 * 2;
    uint32_t sw = off ^ ((off >> 3) & 0x70);
    *(uint4*)(bhi + sw) = *(uint4*)hi;
    *(uint4*)(blo + sw) = *(uint4*)lo;
}

__global__ void k_packB(const float* __restrict__ wfc) {
    int tile = blockIdx.x, kc = blockIdx.y;
    char* bhi = (char*)(g_Bhi + ((size_t)tile * KC + kc) * 8192);
    char* blo = (char*)(g_Blo + ((size_t)tile * KC + kc) * 8192);
    for (int u = threadIdx.x; u < 1024; u += 256) {
        int r = u >> 3, c8 = (u & 7) * 8;
        int n = tile * 128 + r;
        float v[8];
        if (n < VD) {
            float4 a = *(const float4*)&wfc[(size_t)n * HD + kc * 64 + c8];
            float4 b = *(const float4*)&wfc[(size_t)n * HD + kc * 64 + c8 + 4];
            v[0]=a.x; v[1]=a.y; v[2]=a.z; v[3]=a.w; v[4]=b.x; v[5]=b.y; v[6]=b.z; v[7]=b.w;
        } else {
#pragma unroll
            for (int j = 0; j < 8; j++) v[j] = 0.f;
        }
        pack8(v, bhi, blo, r, c8);
    }
}

__global__ void k_packW(const float* __restrict__ wih) {
    int tile = blockIdx.x, kc = blockIdx.y;
    char* bhi = (char*)(g_Whi + ((size_t)tile * KC + kc) * 8192);
    char* blo = (char*)(g_Wlo + ((size_t)tile * KC + kc) * 8192);
    for (int u = threadIdx.x; u < 1024; u += 256) {
        int r = u >> 3, c8 = (u & 7) * 8;
        int n = tile * 128 + r;
        float v[8];
        float4 a = *(const float4*)&wih[(size_t)n * ED + kc * 64 + c8];
        float4 b = *(const float4*)&wih[(size_t)n * ED + kc * 64 + c8 + 4];
        v[0]=a.x; v[1]=a.y; v[2]=a.z; v[3]=a.w; v[4]=b.x; v[5]=b.y; v[6]=b.z; v[7]=b.w;
        pack8(v, bhi, blo, r, c8);
    }
}

// gathered sorted embedding rows (t-major rows; after k_sort)
__global__ void k_packE(const float* __restrict__ emb, const int* __restrict__ caps) {
    int tile = blockIdx.x, kc = blockIdx.y;
    __shared__ int tok[128];
    char* bhi = (char*)(g_Ehi + ((size_t)tile * KC + kc) * 8192);
    char* blo = (char*)(g_Elo + ((size_t)tile * KC + kc) * 8192);
    if (threadIdx.x < 128) {
        int r = threadIdx.x;
        int t = tile * 2 + (r >> 6), b = r & 63;
        tok[r] = caps[g_sort[b] * CL + t];
    }
    __syncthreads();
    for (int u = threadIdx.x; u < 1024; u += 256) {
        int r = u >> 3, c8 = (u & 7) * 8;
        float v[8];
        const float* src = emb + (size_t)tok[r] * ED + kc * 64 + c8;
        float4 a = *(const float4*)src;
        float4 b = *(const float4*)(src + 4);
        v[0]=a.x; v[1]=a.y; v[2]=a.z; v[3]=a.w; v[4]=b.x; v[5]=b.y; v[6]=b.z; v[7]=b.w;
        pack8(v, bhi, blo, r, c8);
    }
}

// ---------------- init h0/c0: K-split partials + fused reduce ----------------
__global__ void k_init_part(const float* __restrict__ enc,
                            const float* __restrict__ wh, const float* __restrict__ wc) {
    __shared__ float As[32][65], Bs[32][65];
    __shared__ int arow[64];
    const float* Wsel = blockIdx.z ? wc : wh;
    int tid = threadIdx.x;
    if (tid < 64) arow[tid] = g_sort[tid];
    __syncthreads();
    int n0 = blockIdx.x * 64;
    int ks = blockIdx.y;
    int tx = tid & 15, ty = tid >> 4;
    int lr = tid >> 2, ls = tid & 3;
    float acc[4][4] = {};
    for (int k0 = ks * 256; k0 < ks * 256 + 256; k0 += 32) {
        const float4* ap = (const float4*)(enc + (size_t)arow[lr] * ENCD + k0);
        stash_tile(As, lr, ls, ap[ls], ap[ls + 4]);
        const float4* bp = (const float4*)(Wsel + (size_t)(n0 + lr) * ENCD + k0);
        stash_tile(Bs, lr, ls, bp[ls], bp[ls + 4]);
        __syncthreads();
        mm_inner(As, Bs, acc, tx, ty);
        __syncthreads();
    }
    float* outp = g_ip[blockIdx.z * 8 + ks];
#pragma unroll
    for (int i = 0; i < 4; i++) {
        int m = ty*4 + i;
#pragma unroll
        for (int j = 0; j < 4; j++)
            outp[m * HD + n0 + tx*4 + j] = acc[i][j];
    }
}

__global__ void k_init_red(const float* __restrict__ bh, const float* __restrict__ bc) {
    int idx = blockIdx.x * 256 + threadIdx.x;
    int z = idx >> 15, r = idx & 32767;
    int n = r & 511;
    float s = 0.f;
#pragma unroll
    for (int p = 0; p < 8; p++) s += g_ip[z * 8 + p][r];
    if (z == 0) g_hbuf[0][r] = s + bh[n];
    else        g_c[r] = s + bc[n];
}

// ---------------- shared mma.sync mainloop (128x128 tile, 3-term bf16, bulk-copy fed) ----------------
__device__ __forceinline__ void mma_mainloop(uint32_t sb, int tid,
        const __nv_bfloat16* Ahi, const __nv_bfloat16* Alo,
        const __nv_bfloat16* Bhi, const __nv_bfloat16* Blo,
        int mtile, int ntile, bool act0, bool act1, float acc[2][8][4]) {
    int lane = tid & 31, warp = tid >> 5;
    int m0 = (warp & 3) * 32, n0w = (warp >> 2) * 64;
    int rl = lane & 7, q = lane >> 3;
    bool mact[2] = {act0, act1};
    uint32_t mb = sb + 131072;
    if (tid == 0) {
        asm volatile("mbarrier.init.shared.b64 [%0], 1;" :: "r"(mb) : "memory");
        asm volatile("mbarrier.init.shared.b64 [%0], 1;" :: "r"(mb + 8) : "memory");
    }
    __syncthreads();
    if (tid == 0) issue_chunk(sb, mb, Ahi, Alo, Bhi, Blo, mtile, ntile, 0);
    for (int c = 0; c < KC; c++) {
        uint32_t st = sb + (uint32_t)(c & 1) * 65536;
        if (tid == 0 && c + 1 < KC)
            issue_chunk(sb + (uint32_t)((c + 1) & 1) * 65536, mb + 8 * ((c + 1) & 1),
                        Ahi, Alo, Bhi, Blo, mtile, ntile, c + 1);
        mbar_wait(mb + 8 * (c & 1), (c >> 1) & 1);
        uint32_t stA = st, stAl = st + 16384, stB = st + 32768, stBl = st + 49152;
#pragma unroll
        for (int s = 0; s < 4; s++) {
            uint32_t bh[8][2], bl[8][2];
#pragma unroll
            for (int g = 0; g < 4; g++) {
                int row = n0w + g * 16 + ((q >> 1) << 3) + rl;
                int off = row * 128 + s * 32 + ((q & 1) << 4);
                int sw = off ^ ((off >> 3) & 0x70);
                uint32_t r0, r1, r2, r3;
                LDSM4(r0, r1, r2, r3, stB + sw);
                bh[g*2][0] = r0; bh[g*2][1] = r1; bh[g*2+1][0] = r2; bh[g*2+1][1] = r3;
                LDSM4(r0, r1, r2, r3, stBl + sw);
                bl[g*2][0] = r0; bl[g*2][1] = r1; bl[g*2+1][0] = r2; bl[g*2+1][1] = r3;
            }
#pragma unroll
            for (int f = 0; f < 2; f++) {
                if (!mact[f]) continue;
                int row = m0 + f * 16 + rl + ((q & 1) << 3);
                int off = row * 128 + s * 32 + ((q >> 1) << 4);
                int sw = off ^ ((off >> 3) & 0x70);
                uint32_t ah[4], al[4];
                LDSM4(ah[0], ah[1], ah[2], ah[3], stA + sw);
                LDSM4(al[0], al[1], al[2], al[3], stAl + sw);
#pragma unroll
                for (int nf = 0; nf < 8; nf++) {
                    MMA16816(acc[f][nf], ah, bh[nf]);
                    MMA16816(acc[f][nf], ah, bl[nf]);
                    MMA16816(acc[f][nf], al, bh[nf]);
                }
            }
        }
        __syncthreads();
    }
}

// ---------------- XW on mma.sync: g_XW = embs @ w_ih^T + b_ih ----------------
__global__ void __launch_bounds__(256, 1)
k_xw_mma(const float* __restrict__ bih) {
    extern __shared__ char smem[];
    uint32_t sb = s2u(smem);
    int tid = threadIdx.x;
    int lane = tid & 31, warp = tid >> 5;
    int m0 = (warp & 3) * 32, n0w = (warp >> 2) * 64;
    int mtile = blockIdx.x % MT, ntile = blockIdx.x / MT;

    float acc[2][8][4];
#pragma unroll
    for (int f = 0; f < 2; f++)
#pragma unroll
        for (int nf = 0; nf < 8; nf++)
#pragma unroll
            for (int e = 0; e < 4; e++) acc[f][nf][e] = 0.f;

    mma_mainloop(sb, tid, g_Ehi, g_Elo, g_Whi, g_Wlo, mtile, ntile, true, true, acc);

#pragma unroll
    for (int f = 0; f < 2; f++) {
        int rbase = mtile * 128 + m0 + f * 16 + (lane >> 2);
#pragma unroll
        for (int rr = 0; rr < 2; rr++) {
            int r = rbase + rr * 8;
            float* orow = g_XW + (size_t)r * GD;
#pragma unroll
            for (int nf = 0; nf < 8; nf++) {
                int n = ntile * 128 + n0w + nf * 8 + ((lane & 3) << 1);
                float2 bb = __ldg((const float2*)&bih[n]);
                float2 v;
                v.x = acc[f][nf][rr * 2 + 0] + bb.x;
                v.y = acc[f][nf][rr * 2 + 1] + bb.y;
                *(float2*)&orow[n] = v;
            }
        }
    }
}

// ---------------- persistent recurrence: 1 global barrier per step, fused pack ----------------
__device__ __forceinline__ void gsync(unsigned target) {
    __syncthreads();
    if (threadIdx.x == 0) {
        __threadfence();
        unsigned old = atomicAdd(&g_cnt, 1);
        if (old == RB - 1) {
            atomicExch(&g_cnt, 0);
            __threadfence();
            atomicAdd(&g_phase, 1);
        } else {
            while ((int)(*(volatile unsigned*)&g_phase - target) < 0) {}
        }
    }
    __syncthreads();
}

// block bi owns output columns j in [bi*4, bi*4+4) across ALL four gates.
__global__ void __launch_bounds__(256, 1) k_rnn(const float* __restrict__ whh,
                                                const float* __restrict__ bhh) {
    extern __shared__ float sm[];
    float* w_s = sm;                       // [k=512][16]  (idx = gate*4 + q)
    float* h_s = sm + 512 * 16;            // [b=64][516]
    float* s_g = sm + 512 * 16 + 64 * 516; // [b=64][16]
    int tid = threadIdx.x, bi = blockIdx.x;
    int j0 = bi * 4;
    for (int i = tid; i < 16 * 512; i += 256) {
        int idx = i >> 9, k = i & 511;
        int n = (idx >> 2) * 512 + j0 + (idx & 3);   // gate=(idx>>2), q=(idx&3)
        w_s[k * 16 + idx] = whh[(size_t)n * HD + k];
    }
    int gb = tid >> 2, gn = tid & 3;       // gemm: batch gb, gate gn (4 q's)
    int pb = gb, q = gn;                   // pointwise: batch pb, column q
    float c_reg = g_c[pb * HD + j0 + q];
    int dl = __ldg(&g_dlen[pb]);
    int cumb = __ldg(&g_cum[pb]);
    float4 b4 = *(const float4*)&bhh[gn * 512 + j0];
    unsigned base = *(volatile unsigned*)&g_phase;
    unsigned lp = 0;
    __syncthreads();
    for (int t = 0; t < NT; t++) {
        const float* hsrc = g_hbuf[t & 1];
        for (int idx = tid; idx < (NB * HD) / 4; idx += 256) {
            int lin = idx * 4;
            int b = lin >> 9, k = lin & 511;
            float4 hv = __ldcg((const float4*)&hsrc[b * HD + k]);
            *(float4*)&h_s[b * 516 + k] = hv;
        }
        __syncthreads();
        float a0 = 0.f, a1 = 0.f, a2 = 0.f, a3 = 0.f;
        const float* hrow = &h_s[gb * 516];
#pragma unroll 8
        for (int k = 0; k < 512; k++) {
            float h = hrow[k];
            float4 w = *(const float4*)&w_s[k * 16 + gn * 4];
            a0 += h * w.x; a1 += h * w.y; a2 += h * w.z; a3 += h * w.w;
        }
        float4 xv = __ldg((const float4*)&g_XW[((size_t)t * NB + gb) * GD + gn * 512 + j0]);
        *(float4*)&s_g[gb * 16 + gn * 4] =
            make_float4(a0 + xv.x + b4.x, a1 + xv.y + b4.y,
                        a2 + xv.z + b4.z, a3 + xv.w + b4.w);
        __syncthreads();
        float gi = s_g[pb * 16 + 0  + q];
        float gf = s_g[pb * 16 + 4  + q];
        float gg = s_g[pb * 16 + 8  + q];
        float go = s_g[pb * 16 + 12 + q];
        float si = 1.f / (1.f + expf(-gi));
        float sf = 1.f / (1.f + expf(-gf));
        float so = 1.f / (1.f + expf(-go));
        c_reg = sf * c_reg + si * tanhf(gg);
        float hv = so * tanhf(c_reg);
        __stcg(&g_hbuf[(t + 1) & 1][pb * HD + j0 + q], hv);
        if (t < dl) {   // fused pack into compacted bf16 A-tiles
            int cr = cumb + t;
            int tile = cr >> 7, r = cr & 127;
            int j = j0 + q, kc = j >> 6, cc = j & 63;
            uint32_t off = (uint32_t)r * 128 + cc * 2;
            uint32_t sw = off ^ ((off >> 3) & 0x70);
            size_t pbase = ((size_t)tile * KC + kc) * 8192 + (sw >> 1);
            __nv_bfloat16 hi = __float2bfloat16(hv);
            __nv_bfloat16 lo = __float2bfloat16(hv - __bfloat162float(hi));
            g_Ahi[pbase] = hi;
            g_Alo[pbase] = lo;
        }
        gsync(base + (++lp));
    }
}

// ---------------- FC on mma.sync over compacted rows ----------------
__global__ void __launch_bounds__(256, 1)
k_fc_mma(const float* __restrict__ bfc, float* __restrict__ out) {
    extern __shared__ char smem[];
    __shared__ int cum_s[65];
    uint32_t sb = s2u(smem);
    int tid = threadIdx.x;
    int lane = tid & 31, warp = tid >> 5;
    int m0 = (warp & 3) * 32, n0w = (warp >> 2) * 64;
    int mtile = blockIdx.x % MT, ntile = blockIdx.x / MT;

    int Atot = __ldg(&g_Atot);
    if (mtile * 128 >= Atot) return;
    if (tid < 65) cum_s[tid] = g_cum[tid];

    bool act0 = (mtile * 128 + m0) < Atot;
    bool act1 = (mtile * 128 + m0 + 16) < Atot;

    float acc[2][8][4];
#pragma unroll
    for (int f = 0; f < 2; f++)
#pragma unroll
        for (int nf = 0; nf < 8; nf++)
#pragma unroll
            for (int e = 0; e < 4; e++) acc[f][nf][e] = 0.f;

    mma_mainloop(sb, tid, g_Ahi, g_Alo, g_Bhi, g_Blo, mtile, ntile, act0, act1, acc);

#pragma unroll
    for (int f = 0; f < 2; f++) {
        int rbase = mtile * 128 + m0 + f * 16 + (lane >> 2);
#pragma unroll
        for (int rr = 0; rr < 2; rr++) {
            int r = rbase + rr * 8;
            if (r >= Atot) continue;
            int lo = 0, hi = 63;
            while (lo < hi) {                 // largest b with cum_s[b] <= r
                int mid = (lo + hi + 1) >> 1;
                if (cum_s[mid] <= r) lo = mid; else hi = mid - 1;
            }
            int b = lo, t = r - cum_s[lo];
            float* orow = out + ((size_t)b * NT + t) * VD;
#pragma unroll
            for (int nf = 0; nf < 8; nf++) {
                int n = ntile * 128 + n0w + nf * 8 + ((lane & 3) << 1);
                if (n < VD) {
                    float2 bb = __ldg((const float2*)&bfc[n]);
                    float2 v;
                    v.x = acc[f][nf][rr * 2 + 0] + bb.x;
                    v.y = acc[f][nf][rr * 2 + 1] + bb.y;
                    *(float2*)&orow[n] = v;
                }
            }
        }
    }
}

// ---------------- launch ----------------
extern "C" void kernel_launch(void* const* d_in, const int* in_sizes, int n_in,
                              void* d_out, int out_size) {
    const float* enc      = (const float*)d_in[0];
    const int*   caps     = (const int*)  d_in[1];
    const int*   clen     = (const int*)  d_in[2];
    const float* emb      = (const float*)d_in[3];
    const float* w_ih     = (const float*)d_in[4];
    const float* b_ih     = (const float*)d_in[5];
    const float* w_hh     = (const float*)d_in[6];
    const float* b_hh     = (const float*)d_in[7];
    const float* w_init_h = (const float*)d_in[8];
    const float* b_init_h = (const float*)d_in[9];
    const float* w_init_c = (const float*)d_in[10];
    const float* b_init_c = (const float*)d_in[11];
    const float* w_fc     = (const float*)d_in[12];
    const float* b_fc     = (const float*)d_in[13];
    float* out = (float*)d_out;

    const long long pred_elems = (long long)NB * NT * VD;
    int extras = ((long long)out_size > pred_elems) ? 1 : 0;

    const int rnn_smem = (512 * 16 + 64 * 516 + 64 * 16) * 4;   // 168960
    const int fc_smem  = 2 * 65536 + 128;                       // stages + mbarriers
    cudaFuncSetAttribute(k_rnn,    cudaFuncAttributeMaxDynamicSharedMemorySize, rnn_smem);
    cudaFuncSetAttribute(k_fc_mma, cudaFuncAttributeMaxDynamicSharedMemorySize, fc_smem);
    cudaFuncSetAttribute(k_xw_mma, cudaFuncAttributeMaxDynamicSharedMemorySize, fc_smem);

    k_sort<<<1, 256>>>(clen, caps, out + pred_elems, extras);
    k_zero<<<NB * NT, 256>>>(out);
    k_packB<<<dim3(NTB, KC), 256>>>(w_fc);
    k_packW<<<dim3(NTW, KC), 256>>>(w_ih);
    k_packE<<<dim3(MT, KC), 256>>>(emb, caps);
    k_init_part<<<dim3(HD / 64, 8, 2), 256>>>(enc, w_init_h, w_init_c);
    k_init_red<<<256, 256>>>(b_init_h, b_init_c);
    k_xw_mma<<<MT * NTW, 256, fc_smem>>>(b_ih);
    k_rnn<<<RB, 256, rnn_smem>>>(w_hh, b_hh);
    k_fc_mma<<<MT * NTB, 256, fc_smem>>>(b_fc, out);
}

// round 14
// speedup vs baseline: 2.9027x; 1.1498x over previous
#include <cuda_runtime.h>
#include <cuda_fp16.h>
#include <math.h>
#include <stdint.h>

#define NB   64
#define CL   51
#define NT   50
#define ED   512
#define HD   512
#define VD   30000
#define ENCD 2048
#define GD   2048

#define MT   25      // max M tiles (128 rows)
#define NTB  235     // FC N tiles (128 vocab rows) -> 30080 padded
#define NTW  16      // XW N tiles (2048 / 128)
#define KC   8       // K chunks of 64
#define RB   128     // persistent rnn blocks

// ---------------- device scratch ----------------
__device__ int      g_sort[NB];
__device__ int      g_dlen[NB];
__device__ int      g_cum[NB + 1];
__device__ int      g_Atot;
__device__ float    g_hbuf[2][NB * HD];
__device__ float    g_c[NB * HD];
__device__ float    g_XW[(size_t)NT * NB * GD];
__device__ float    g_ip[16][NB * HD];
__device__ unsigned g_cnt;
__device__ unsigned g_phase;

// packed fp16 SW128-swizzled tiles: [tile][kc][128 rows x 64 k] = 8192 halves (16KB)
__device__ __align__(128) __half g_Bf [(size_t)NTB * KC * 8192];   // w_fc single fp16
__device__ __align__(128) __half g_Ahi[(size_t)MT  * KC * 8192];   // compacted active h rows
__device__ __align__(128) __half g_Alo[(size_t)MT  * KC * 8192];
__device__ __align__(128) __half g_Whi[(size_t)NTW * KC * 8192];
__device__ __align__(128) __half g_Wlo[(size_t)NTW * KC * 8192];
__device__ __align__(128) __half g_Ehi[(size_t)MT  * KC * 8192];
__device__ __align__(128) __half g_Elo[(size_t)MT  * KC * 8192];

// ---------------- PTX helpers ----------------
__device__ __forceinline__ uint32_t s2u(const void* p) {
    uint32_t a;
    asm("{ .reg .u64 t; cvta.to.shared.u64 t, %1; cvt.u32.u64 %0, t; }" : "=r"(a) : "l"(p));
    return a;
}
#define LDSM4(r0, r1, r2, r3, addr) \
    asm volatile("ldmatrix.sync.aligned.m8n8.x4.shared.b16 {%0,%1,%2,%3}, [%4];" \
        : "=r"(r0), "=r"(r1), "=r"(r2), "=r"(r3) : "r"(addr))
#define MMA16816(d, a, b) \
    asm volatile("mma.sync.aligned.m16n8k16.row.col.f32.f16.f16.f32 " \
        "{%0,%1,%2,%3},{%4,%5,%6,%7},{%8,%9},{%0,%1,%2,%3};" \
        : "+f"((d)[0]), "+f"((d)[1]), "+f"((d)[2]), "+f"((d)[3]) \
        : "r"((a)[0]), "r"((a)[1]), "r"((a)[2]), "r"((a)[3]), "r"((b)[0]), "r"((b)[1]))

__device__ __forceinline__ void mbar_wait(uint32_t mbar, uint32_t parity) {
    asm volatile(
        "{\n\t.reg .pred P;\n\tLW_%=: \n\t"
        "mbarrier.try_wait.parity.shared.b64 P, [%0], %1;\n\t"
        "@P bra LD_%=;\n\tbra LW_%=;\n\tLD_%=: \n\t}"
        :: "r"(mbar), "r"(parity) : "memory");
}
__device__ __forceinline__ void bulk16k(uint32_t dst, const void* src, uint32_t mbar) {
    asm volatile(
        "cp.async.bulk.shared::cta.global.mbarrier::complete_tx::bytes [%0], [%1], %2, [%3];"
        :: "r"(dst), "l"(src), "r"(16384u), "r"(mbar) : "memory");
}

// ---------------- fp32 GEMM tile helpers (init GEMM) ----------------
__device__ __forceinline__ void stash_tile(float (*S)[65], int lr, int ls, float4 v0, float4 v1) {
    S[ls*4+0][lr] = v0.x; S[ls*4+1][lr] = v0.y; S[ls*4+2][lr] = v0.z; S[ls*4+3][lr] = v0.w;
    S[16+ls*4+0][lr] = v1.x; S[16+ls*4+1][lr] = v1.y; S[16+ls*4+2][lr] = v1.z; S[16+ls*4+3][lr] = v1.w;
}
__device__ __forceinline__ void mm_inner(float (*As)[65], float (*Bs)[65],
                                         float acc[4][4], int tx, int ty) {
#pragma unroll
    for (int kk = 0; kk < 32; kk++) {
        float a0 = As[kk][ty*4+0], a1 = As[kk][ty*4+1];
        float a2 = As[kk][ty*4+2], a3 = As[kk][ty*4+3];
        float b0 = Bs[kk][tx*4+0], b1 = Bs[kk][tx*4+1];
        float b2 = Bs[kk][tx*4+2], b3 = Bs[kk][tx*4+3];
        acc[0][0] += a0*b0; acc[0][1] += a0*b1; acc[0][2] += a0*b2; acc[0][3] += a0*b3;
        acc[1][0] += a1*b0; acc[1][1] += a1*b1; acc[1][2] += a1*b2; acc[1][3] += a1*b3;
        acc[2][0] += a2*b0; acc[2][1] += a2*b1; acc[2][2] += a2*b2; acc[2][3] += a2*b3;
        acc[3][0] += a3*b0; acc[3][1] += a3*b1; acc[3][2] += a3*b2; acc[3][3] += a3*b3;
    }
}

// ---------------- sort + cum + extras ----------------
__global__ void k_sort(const int* __restrict__ lens, const int* __restrict__ caps,
                       float* __restrict__ out_extra, int extras) {
    __shared__ int slen[NB];
    __shared__ int sidx[NB];
    int t = threadIdx.x;
    if (t < NB) slen[t] = lens[t];
    __syncthreads();
    if (t < NB) {
        int Li = slen[t];
        int r = 0;
        for (int j = 0; j < NB; j++) {
            int Lj = slen[j];
            if (Lj > Li || (Lj == Li && j < t)) r++;
        }
        sidx[r] = t;
    }
    __syncthreads();
    if (t < NB) { g_sort[t] = sidx[t]; g_dlen[t] = slen[sidx[t]] - 1; }
    __syncthreads();
    if (t == 0) {
        int s = 0;
        for (int b = 0; b < NB; b++) { g_cum[b] = s; s += slen[sidx[b]] - 1; }
        g_cum[NB] = s;
        g_Atot = s;
    }
    if (extras) {
        for (int i = t; i < NB * CL; i += blockDim.x) {
            int b = i / CL, j = i % CL;
            out_extra[i] = (float)caps[sidx[b] * CL + j];
        }
        if (t < NB) out_extra[NB*CL + t]      = (float)(slen[sidx[t]] - 1);
        if (t < NB) out_extra[NB*CL + NB + t] = (float)sidx[t];
    }
}

// ---------------- zero inactive output rows ----------------
__global__ void k_zero(float* __restrict__ out) {
    int b = blockIdx.x / NT, t = blockIdx.x % NT;
    if (t < g_dlen[b]) return;
    float4 z = make_float4(0.f, 0.f, 0.f, 0.f);
    float* row = out + ((size_t)b * NT + t) * VD;
    for (int i = threadIdx.x * 4; i < VD; i += 256 * 4)
        *(float4*)&row[i] = z;
}

// ---------------- packers: fp32 -> swizzled fp16, 16B vectorized ----------------
__device__ __forceinline__ void pack8_hl(const float v[8], char* bhi, char* blo, int r, int c8) {
    __align__(16) __half hi[8], lo[8];
#pragma unroll
    for (int j = 0; j < 8; j++) {
        hi[j] = __float2half_rn(v[j]);
        lo[j] = __float2half_rn(v[j] - __half2float(hi[j]));
    }
    uint32_t off = (uint32_t)r * 128 + c8 * 2;
    uint32_t sw = off ^ ((off >> 3) & 0x70);
    *(uint4*)(bhi + sw) = *(uint4*)hi;
    *(uint4*)(blo + sw) = *(uint4*)lo;
}
__device__ __forceinline__ void pack8_s(const float v[8], char* bf, int r, int c8) {
    __align__(16) __half h[8];
#pragma unroll
    for (int j = 0; j < 8; j++) h[j] = __float2half_rn(v[j]);
    uint32_t off = (uint32_t)r * 128 + c8 * 2;
    uint32_t sw = off ^ ((off >> 3) & 0x70);
    *(uint4*)(bf + sw) = *(uint4*)h;
}

__global__ void k_packB(const float* __restrict__ wfc) {
    int tile = blockIdx.x, kc = blockIdx.y;
    char* bf = (char*)(g_Bf + ((size_t)tile * KC + kc) * 8192);
    for (int u = threadIdx.x; u < 1024; u += 256) {
        int r = u >> 3, c8 = (u & 7) * 8;
        int n = tile * 128 + r;
        float v[8];
        if (n < VD) {
            float4 a = *(const float4*)&wfc[(size_t)n * HD + kc * 64 + c8];
            float4 b = *(const float4*)&wfc[(size_t)n * HD + kc * 64 + c8 + 4];
            v[0]=a.x; v[1]=a.y; v[2]=a.z; v[3]=a.w; v[4]=b.x; v[5]=b.y; v[6]=b.z; v[7]=b.w;
        } else {
#pragma unroll
            for (int j = 0; j < 8; j++) v[j] = 0.f;
        }
        pack8_s(v, bf, r, c8);
    }
}

__global__ void k_packW(const float* __restrict__ wih) {
    int tile = blockIdx.x, kc = blockIdx.y;
    char* bhi = (char*)(g_Whi + ((size_t)tile * KC + kc) * 8192);
    char* blo = (char*)(g_Wlo + ((size_t)tile * KC + kc) * 8192);
    for (int u = threadIdx.x; u < 1024; u += 256) {
        int r = u >> 3, c8 = (u & 7) * 8;
        int n = tile * 128 + r;
        float v[8];
        float4 a = *(const float4*)&wih[(size_t)n * ED + kc * 64 + c8];
        float4 b = *(const float4*)&wih[(size_t)n * ED + kc * 64 + c8 + 4];
        v[0]=a.x; v[1]=a.y; v[2]=a.z; v[3]=a.w; v[4]=b.x; v[5]=b.y; v[6]=b.z; v[7]=b.w;
        pack8_hl(v, bhi, blo, r, c8);
    }
}

// gathered sorted embedding rows (t-major rows; after k_sort)
__global__ void k_packE(const float* __restrict__ emb, const int* __restrict__ caps) {
    int tile = blockIdx.x, kc = blockIdx.y;
    __shared__ int tok[128];
    char* bhi = (char*)(g_Ehi + ((size_t)tile * KC + kc) * 8192);
    char* blo = (char*)(g_Elo + ((size_t)tile * KC + kc) * 8192);
    if (threadIdx.x < 128) {
        int r = threadIdx.x;
        int t = tile * 2 + (r >> 6), b = r & 63;
        tok[r] = caps[g_sort[b] * CL + t];
    }
    __syncthreads();
    for (int u = threadIdx.x; u < 1024; u += 256) {
        int r = u >> 3, c8 = (u & 7) * 8;
        float v[8];
        const float* src = emb + (size_t)tok[r] * ED + kc * 64 + c8;
        float4 a = *(const float4*)src;
        float4 b = *(const float4*)(src + 4);
        v[0]=a.x; v[1]=a.y; v[2]=a.z; v[3]=a.w; v[4]=b.x; v[5]=b.y; v[6]=b.z; v[7]=b.w;
        pack8_hl(v, bhi, blo, r, c8);
    }
}

// ---------------- init h0/c0: K-split partials + fused reduce ----------------
__global__ void k_init_part(const float* __restrict__ enc,
                            const float* __restrict__ wh, const float* __restrict__ wc) {
    __shared__ float As[32][65], Bs[32][65];
    __shared__ int arow[64];
    const float* Wsel = blockIdx.z ? wc : wh;
    int tid = threadIdx.x;
    if (tid < 64) arow[tid] = g_sort[tid];
    __syncthreads();
    int n0 = blockIdx.x * 64;
    int ks = blockIdx.y;
    int tx = tid & 15, ty = tid >> 4;
    int lr = tid >> 2, ls = tid & 3;
    float acc[4][4] = {};
    for (int k0 = ks * 256; k0 < ks * 256 + 256; k0 += 32) {
        const float4* ap = (const float4*)(enc + (size_t)arow[lr] * ENCD + k0);
        stash_tile(As, lr, ls, ap[ls], ap[ls + 4]);
        const float4* bp = (const float4*)(Wsel + (size_t)(n0 + lr) * ENCD + k0);
        stash_tile(Bs, lr, ls, bp[ls], bp[ls + 4]);
        __syncthreads();
        mm_inner(As, Bs, acc, tx, ty);
        __syncthreads();
    }
    float* outp = g_ip[blockIdx.z * 8 + ks];
#pragma unroll
    for (int i = 0; i < 4; i++) {
        int m = ty*4 + i;
#pragma unroll
        for (int j = 0; j < 4; j++)
            outp[m * HD + n0 + tx*4 + j] = acc[i][j];
    }
}

__global__ void k_init_red(const float* __restrict__ bh, const float* __restrict__ bc) {
    int idx = blockIdx.x * 256 + threadIdx.x;
    int z = idx >> 15, r = idx & 32767;
    int n = r & 511;
    float s = 0.f;
#pragma unroll
    for (int p = 0; p < 8; p++) s += g_ip[z * 8 + p][r];
    if (z == 0) g_hbuf[0][r] = s + bh[n];
    else        g_c[r] = s + bc[n];
}

// ---------------- shared mma.sync mainloop (128x128 tile, fp16, bulk-copy fed) ----------------
// BSPLIT=true : 3-term (AhiBhi + AhiBlo + AloBhi), chunk = 64KB
// BSPLIT=false: 2-term (AhiB + AloB),              chunk = 48KB
template<bool BSPLIT>
__device__ __forceinline__ void mma_mainloop(uint32_t sb, int tid,
        const __half* Ahi, const __half* Alo,
        const __half* Bhi, const __half* Blo,
        int mtile, int ntile, bool act0, bool act1, float acc[2][8][4]) {
    const uint32_t CHUNK = BSPLIT ? 65536u : 49152u;
    int lane = tid & 31, warp = tid >> 5;
    int m0 = (warp & 3) * 32, n0w = (warp >> 2) * 64;
    int rl = lane & 7, q = lane >> 3;
    bool mact[2] = {act0, act1};
    uint32_t mb = sb + 2 * CHUNK;
    if (tid == 0) {
        asm volatile("mbarrier.init.shared.b64 [%0], 1;" :: "r"(mb) : "memory");
        asm volatile("mbarrier.init.shared.b64 [%0], 1;" :: "r"(mb + 8) : "memory");
    }
    __syncthreads();
    if (tid == 0) {
        asm volatile("mbarrier.arrive.expect_tx.shared.b64 _, [%0], %1;"
                     :: "r"(mb), "r"(CHUNK) : "memory");
        bulk16k(sb,         Ahi + ((size_t)mtile * KC) * 8192, mb);
        bulk16k(sb + 16384, Alo + ((size_t)mtile * KC) * 8192, mb);
        bulk16k(sb + 32768, Bhi + ((size_t)ntile * KC) * 8192, mb);
        if (BSPLIT) bulk16k(sb + 49152, Blo + ((size_t)ntile * KC) * 8192, mb);
    }
    for (int c = 0; c < KC; c++) {
        uint32_t st = sb + (uint32_t)(c & 1) * CHUNK;
        if (tid == 0 && c + 1 < KC) {
            uint32_t st2 = sb + (uint32_t)((c + 1) & 1) * CHUNK;
            uint32_t mb2 = mb + 8 * ((c + 1) & 1);
            asm volatile("mbarrier.arrive.expect_tx.shared.b64 _, [%0], %1;"
                         :: "r"(mb2), "r"(CHUNK) : "memory");
            bulk16k(st2,         Ahi + ((size_t)mtile * KC + c + 1) * 8192, mb2);
            bulk16k(st2 + 16384, Alo + ((size_t)mtile * KC + c + 1) * 8192, mb2);
            bulk16k(st2 + 32768, Bhi + ((size_t)ntile * KC + c + 1) * 8192, mb2);
            if (BSPLIT) bulk16k(st2 + 49152, Blo + ((size_t)ntile * KC + c + 1) * 8192, mb2);
        }
        mbar_wait(mb + 8 * (c & 1), (c >> 1) & 1);
        uint32_t stA = st, stAl = st + 16384, stB = st + 32768, stBl = st + 49152;
#pragma unroll
        for (int s = 0; s < 4; s++) {
            uint32_t bh[8][2], bl[8][2];
#pragma unroll
            for (int g = 0; g < 4; g++) {
                int row = n0w + g * 16 + ((q >> 1) << 3) + rl;
                int off = row * 128 + s * 32 + ((q & 1) << 4);
                int sw = off ^ ((off >> 3) & 0x70);
                uint32_t r0, r1, r2, r3;
                LDSM4(r0, r1, r2, r3, stB + sw);
                bh[g*2][0] = r0; bh[g*2][1] = r1; bh[g*2+1][0] = r2; bh[g*2+1][1] = r3;
                if (BSPLIT) {
                    LDSM4(r0, r1, r2, r3, stBl + sw);
                    bl[g*2][0] = r0; bl[g*2][1] = r1; bl[g*2+1][0] = r2; bl[g*2+1][1] = r3;
                }
            }
#pragma unroll
            for (int f = 0; f < 2; f++) {
                if (!mact[f]) continue;
                int row = m0 + f * 16 + rl + ((q & 1) << 3);
                int off = row * 128 + s * 32 + ((q >> 1) << 4);
                int sw = off ^ ((off >> 3) & 0x70);
                uint32_t ah[4], al[4];
                LDSM4(ah[0], ah[1], ah[2], ah[3], stA + sw);
                LDSM4(al[0], al[1], al[2], al[3], stAl + sw);
#pragma unroll
                for (int nf = 0; nf < 8; nf++) {
                    MMA16816(acc[f][nf], ah, bh[nf]);
                    if (BSPLIT) MMA16816(acc[f][nf], ah, bl[nf]);
                    MMA16816(acc[f][nf], al, bh[nf]);
                }
            }
        }
        __syncthreads();
    }
}

// ---------------- XW on mma.sync: g_XW = embs @ w_ih^T + b_ih (3-term fp16) ----------------
__global__ void __launch_bounds__(256, 1)
k_xw_mma(const float* __restrict__ bih) {
    extern __shared__ char smem[];
    uint32_t sb = s2u(smem);
    int tid = threadIdx.x;
    int lane = tid & 31, warp = tid >> 5;
    int m0 = (warp & 3) * 32, n0w = (warp >> 2) * 64;
    int mtile = blockIdx.x % MT, ntile = blockIdx.x / MT;

    float acc[2][8][4];
#pragma unroll
    for (int f = 0; f < 2; f++)
#pragma unroll
        for (int nf = 0; nf < 8; nf++)
#pragma unroll
            for (int e = 0; e < 4; e++) acc[f][nf][e] = 0.f;

    mma_mainloop<true>(sb, tid, g_Ehi, g_Elo, g_Whi, g_Wlo, mtile, ntile, true, true, acc);

#pragma unroll
    for (int f = 0; f < 2; f++) {
        int rbase = mtile * 128 + m0 + f * 16 + (lane >> 2);
#pragma unroll
        for (int rr = 0; rr < 2; rr++) {
            int r = rbase + rr * 8;
            float* orow = g_XW + (size_t)r * GD;
#pragma unroll
            for (int nf = 0; nf < 8; nf++) {
                int n = ntile * 128 + n0w + nf * 8 + ((lane & 3) << 1);
                float2 bb = __ldg((const float2*)&bih[n]);
                float2 v;
                v.x = acc[f][nf][rr * 2 + 0] + bb.x;
                v.y = acc[f][nf][rr * 2 + 1] + bb.y;
                *(float2*)&orow[n] = v;
            }
        }
    }
}

// ---------------- persistent recurrence: 1 global barrier per step, fused pack ----------------
__device__ __forceinline__ void gsync(unsigned target) {
    __syncthreads();
    if (threadIdx.x == 0) {
        __threadfence();
        unsigned old = atomicAdd(&g_cnt, 1);
        if (old == RB - 1) {
            atomicExch(&g_cnt, 0);
            __threadfence();
            atomicAdd(&g_phase, 1);
        } else {
            while ((int)(*(volatile unsigned*)&g_phase - target) < 0) {}
        }
    }
    __syncthreads();
}

// block bi owns output columns j in [bi*4, bi*4+4) across ALL four gates.
__global__ void __launch_bounds__(256, 1) k_rnn(const float* __restrict__ whh,
                                                const float* __restrict__ bhh) {
    extern __shared__ float sm[];
    float* w_s = sm;                       // [k=512][16]  (idx = gate*4 + q)
    float* h_s = sm + 512 * 16;            // [b=64][516]
    float* s_g = sm + 512 * 16 + 64 * 516; // [b=64][16]
    int tid = threadIdx.x, bi = blockIdx.x;
    int j0 = bi * 4;
    for (int i = tid; i < 16 * 512; i += 256) {
        int idx = i >> 9, k = i & 511;
        int n = (idx >> 2) * 512 + j0 + (idx & 3);   // gate=(idx>>2), q=(idx&3)
        w_s[k * 16 + idx] = whh[(size_t)n * HD + k];
    }
    int gb = tid >> 2, gn = tid & 3;       // gemm: batch gb, gate gn (4 q's)
    int pb = gb, q = gn;                   // pointwise: batch pb, column q
    float c_reg = g_c[pb * HD + j0 + q];
    int dl = __ldg(&g_dlen[pb]);
    int cumb = __ldg(&g_cum[pb]);
    float4 b4 = *(const float4*)&bhh[gn * 512 + j0];
    unsigned base = *(volatile unsigned*)&g_phase;
    unsigned lp = 0;
    __syncthreads();
    for (int t = 0; t < NT; t++) {
        const float* hsrc = g_hbuf[t & 1];
        for (int idx = tid; idx < (NB * HD) / 4; idx += 256) {
            int lin = idx * 4;
            int b = lin >> 9, k = lin & 511;
            float4 hv = __ldcg((const float4*)&hsrc[b * HD + k]);
            *(float4*)&h_s[b * 516 + k] = hv;
        }
        __syncthreads();
        float a0 = 0.f, a1 = 0.f, a2 = 0.f, a3 = 0.f;
        const float* hrow = &h_s[gb * 516];
#pragma unroll 8
        for (int k = 0; k < 512; k++) {
            float h = hrow[k];
            float4 w = *(const float4*)&w_s[k * 16 + gn * 4];
            a0 += h * w.x; a1 += h * w.y; a2 += h * w.z; a3 += h * w.w;
        }
        float4 xv = __ldg((const float4*)&g_XW[((size_t)t * NB + gb) * GD + gn * 512 + j0]);
        *(float4*)&s_g[gb * 16 + gn * 4] =
            make_float4(a0 + xv.x + b4.x, a1 + xv.y + b4.y,
                        a2 + xv.z + b4.z, a3 + xv.w + b4.w);
        __syncthreads();
        float gi = s_g[pb * 16 + 0  + q];
        float gf = s_g[pb * 16 + 4  + q];
        float gg = s_g[pb * 16 + 8  + q];
        float go = s_g[pb * 16 + 12 + q];
        float si = 1.f / (1.f + expf(-gi));
        float sf = 1.f / (1.f + expf(-gf));
        float so = 1.f / (1.f + expf(-go));
        c_reg = sf * c_reg + si * tanhf(gg);
        float hv = so * tanhf(c_reg);
        __stcg(&g_hbuf[(t + 1) & 1][pb * HD + j0 + q], hv);
        if (t < dl) {   // fused pack into compacted fp16 A-tiles
            int cr = cumb + t;
            int tile = cr >> 7, r = cr & 127;
            int j = j0 + q, kc = j >> 6, cc = j & 63;
            uint32_t off = (uint32_t)r * 128 + cc * 2;
            uint32_t sw = off ^ ((off >> 3) & 0x70);
            size_t pbase = ((size_t)tile * KC + kc) * 8192 + (sw >> 1);
            __half hi = __float2half_rn(hv);
            __half lo = __float2half_rn(hv - __half2float(hi));
            g_Ahi[pbase] = hi;
            g_Alo[pbase] = lo;
        }
        gsync(base + (++lp));
    }
}

// ---------------- FC on mma.sync over compacted rows (2-term fp16) ----------------
__global__ void __launch_bounds__(256, 1)
k_fc_mma(const float* __restrict__ bfc, float* __restrict__ out) {
    extern __shared__ char smem[];
    __shared__ int cum_s[65];
    uint32_t sb = s2u(smem);
    int tid = threadIdx.x;
    int lane = tid & 31, warp = tid >> 5;
    int m0 = (warp & 3) * 32, n0w = (warp >> 2) * 64;
    int mtile = blockIdx.x % MT, ntile = blockIdx.x / MT;

    int Atot = __ldg(&g_Atot);
    if (mtile * 128 >= Atot) return;
    if (tid < 65) cum_s[tid] = g_cum[tid];

    bool act0 = (mtile * 128 + m0) < Atot;
    bool act1 = (mtile * 128 + m0 + 16) < Atot;

    float acc[2][8][4];
#pragma unroll
    for (int f = 0; f < 2; f++)
#pragma unroll
        for (int nf = 0; nf < 8; nf++)
#pragma unroll
            for (int e = 0; e < 4; e++) acc[f][nf][e] = 0.f;

    mma_mainloop<false>(sb, tid, g_Ahi, g_Alo, g_Bf, (const __half*)0,
                        mtile, ntile, act0, act1, acc);

#pragma unroll
    for (int f = 0; f < 2; f++) {
        int rbase = mtile * 128 + m0 + f * 16 + (lane >> 2);
#pragma unroll
        for (int rr = 0; rr < 2; rr++) {
            int r = rbase + rr * 8;
            if (r >= Atot) continue;
            int lo = 0, hi = 63;
            while (lo < hi) {                 // largest b with cum_s[b] <= r
                int mid = (lo + hi + 1) >> 1;
                if (cum_s[mid] <= r) lo = mid; else hi = mid - 1;
            }
            int b = lo, t = r - cum_s[lo];
            float* orow = out + ((size_t)b * NT + t) * VD;
#pragma unroll
            for (int nf = 0; nf < 8; nf++) {
                int n = ntile * 128 + n0w + nf * 8 + ((lane & 3) << 1);
                if (n < VD) {
                    float2 bb = __ldg((const float2*)&bfc[n]);
                    float2 v;
                    v.x = acc[f][nf][rr * 2 + 0] + bb.x;
                    v.y = acc[f][nf][rr * 2 + 1] + bb.y;
                    *(float2*)&orow[n] = v;
                }
            }
        }
    }
}

// ---------------- launch ----------------
extern "C" void kernel_launch(void* const* d_in, const int* in_sizes, int n_in,
                              void* d_out, int out_size) {
    const float* enc      = (const float*)d_in[0];
    const int*   caps     = (const int*)  d_in[1];
    const int*   clen     = (const int*)  d_in[2];
    const float* emb      = (const float*)d_in[3];
    const float* w_ih     = (const float*)d_in[4];
    const float* b_ih     = (const float*)d_in[5];
    const float* w_hh     = (const float*)d_in[6];
    const float* b_hh     = (const float*)d_in[7];
    const float* w_init_h = (const float*)d_in[8];
    const float* b_init_h = (const float*)d_in[9];
    const float* w_init_c = (const float*)d_in[10];
    const float* b_init_c = (const float*)d_in[11];
    const float* w_fc     = (const float*)d_in[12];
    const float* b_fc     = (const float*)d_in[13];
    float* out = (float*)d_out;

    const long long pred_elems = (long long)NB * NT * VD;
    int extras = ((long long)out_size > pred_elems) ? 1 : 0;

    const int rnn_smem = (512 * 16 + 64 * 516 + 64 * 16) * 4;   // 168960
    const int xw_smem  = 2 * 65536 + 128;
    const int fc_smem  = 2 * 49152 + 128;
    cudaFuncSetAttribute(k_rnn,    cudaFuncAttributeMaxDynamicSharedMemorySize, rnn_smem);
    cudaFuncSetAttribute(k_fc_mma, cudaFuncAttributeMaxDynamicSharedMemorySize, fc_smem);
    cudaFuncSetAttribute(k_xw_mma, cudaFuncAttributeMaxDynamicSharedMemorySize, xw_smem);

    k_sort<<<1, 256>>>(clen, caps, out + pred_elems, extras);
    k_zero<<<NB * NT, 256>>>(out);
    k_packB<<<dim3(NTB, KC), 256>>>(w_fc);
    k_packW<<<dim3(NTW, KC), 256>>>(w_ih);
    k_packE<<<dim3(MT, KC), 256>>>(emb, caps);
    k_init_part<<<dim3(HD / 64, 8, 2), 256>>>(enc, w_init_h, w_init_c);
    k_init_red<<<256, 256>>>(b_init_h, b_init_c);
    k_xw_mma<<<MT * NTW, 256, xw_smem>>>(b_ih);
    k_rnn<<<RB, 256, rnn_smem>>>(w_hh, b_hh);
    k_fc_mma<<<MT * NTB, 256, fc_smem>>>(b_fc, out);
}

// round 17
// speedup vs baseline: 3.1469x; 1.0841x over previous
#include <cuda_runtime.h>
#include <cuda_fp16.h>
#include <math.h>
#include <stdint.h>

#define NB   64
#define CL   51
#define NT   50
#define ED   512
#define HD   512
#define VD   30000
#define ENCD 2048
#define GD   2048

#define MT   25      // max M tiles (128 rows)
#define NTB  235     // FC N tiles (128 vocab rows) -> 30080 padded
#define NTW  16      // XW N tiles (2048 / 128)
#define KC   8       // K chunks of 64
#define RB   128     // persistent rnn blocks

// ---------------- device scratch ----------------
__device__ int      g_sort[NB];
__device__ int      g_dlen[NB];
__device__ int      g_cum[NB + 1];
__device__ int      g_Atot;
__device__ float    g_hbuf[2][NB * HD];
__device__ float    g_c[NB * HD];
__device__ float    g_XW[(size_t)NT * NB * GD];
__device__ float    g_ip[16][NB * HD];
__device__ unsigned g_cnt;
__device__ unsigned g_phase;

// packed fp16 SW128-swizzled tiles: [tile][kc][128 rows x 64 k] = 8192 halves (16KB)
__device__ __align__(128) __half g_Bf [(size_t)NTB * KC * 8192];   // w_fc single fp16
__device__ __align__(128) __half g_Af [(size_t)MT  * KC * 8192];   // compacted active h rows (single fp16)
__device__ __align__(128) __half g_Whi[(size_t)NTW * KC * 8192];   // w_ih single fp16
__device__ __align__(128) __half g_Ehi[(size_t)MT  * KC * 8192];
__device__ __align__(128) __half g_Elo[(size_t)MT  * KC * 8192];

// ---------------- PTX helpers ----------------
__device__ __forceinline__ uint32_t s2u(const void* p) {
    uint32_t a;
    asm("{ .reg .u64 t; cvta.to.shared.u64 t, %1; cvt.u32.u64 %0, t; }" : "=r"(a) : "l"(p));
    return a;
}
#define LDSM4(r0, r1, r2, r3, addr) \
    asm volatile("ldmatrix.sync.aligned.m8n8.x4.shared.b16 {%0,%1,%2,%3}, [%4];" \
        : "=r"(r0), "=r"(r1), "=r"(r2), "=r"(r3) : "r"(addr))
#define MMA16816(d, a, b) \
    asm volatile("mma.sync.aligned.m16n8k16.row.col.f32.f16.f16.f32 " \
        "{%0,%1,%2,%3},{%4,%5,%6,%7},{%8,%9},{%0,%1,%2,%3};" \
        : "+f"((d)[0]), "+f"((d)[1]), "+f"((d)[2]), "+f"((d)[3]) \
        : "r"((a)[0]), "r"((a)[1]), "r"((a)[2]), "r"((a)[3]), "r"((b)[0]), "r"((b)[1]))

__device__ __forceinline__ void mbar_wait(uint32_t mbar, uint32_t parity) {
    asm volatile(
        "{\n\t.reg .pred P;\n\tLW_%=: \n\t"
        "mbarrier.try_wait.parity.shared.b64 P, [%0], %1;\n\t"
        "@P bra LD_%=;\n\tbra LW_%=;\n\tLD_%=: \n\t}"
        :: "r"(mbar), "r"(parity) : "memory");
}
__device__ __forceinline__ void bulk16k(uint32_t dst, const void* src, uint32_t mbar) {
    asm volatile(
        "cp.async.bulk.shared::cta.global.mbarrier::complete_tx::bytes [%0], [%1], %2, [%3];"
        :: "r"(dst), "l"(src), "r"(16384u), "r"(mbar) : "memory");
}

// ---------------- fp32 GEMM tile helpers (init GEMM) ----------------
__device__ __forceinline__ void stash_tile(float (*S)[65], int lr, int ls, float4 v0, float4 v1) {
    S[ls*4+0][lr] = v0.x; S[ls*4+1][lr] = v0.y; S[ls*4+2][lr] = v0.z; S[ls*4+3][lr] = v0.w;
    S[16+ls*4+0][lr] = v1.x; S[16+ls*4+1][lr] = v1.y; S[16+ls*4+2][lr] = v1.z; S[16+ls*4+3][lr] = v1.w;
}
__device__ __forceinline__ void mm_inner(float (*As)[65], float (*Bs)[65],
                                         float acc[4][4], int tx, int ty) {
#pragma unroll
    for (int kk = 0; kk < 32; kk++) {
        float a0 = As[kk][ty*4+0], a1 = As[kk][ty*4+1];
        float a2 = As[kk][ty*4+2], a3 = As[kk][ty*4+3];
        float b0 = Bs[kk][tx*4+0], b1 = Bs[kk][tx*4+1];
        float b2 = Bs[kk][tx*4+2], b3 = Bs[kk][tx*4+3];
        acc[0][0] += a0*b0; acc[0][1] += a0*b1; acc[0][2] += a0*b2; acc[0][3] += a0*b3;
        acc[1][0] += a1*b0; acc[1][1] += a1*b1; acc[1][2] += a1*b2; acc[1][3] += a1*b3;
        acc[2][0] += a2*b0; acc[2][1] += a2*b1; acc[2][2] += a2*b2; acc[2][3] += a2*b3;
        acc[3][0] += a3*b0; acc[3][1] += a3*b1; acc[3][2] += a3*b2; acc[3][3] += a3*b3;
    }
}

// ---------------- sort + cum + extras ----------------
__global__ void k_sort(const int* __restrict__ lens, const int* __restrict__ caps,
                       float* __restrict__ out_extra, int extras) {
    __shared__ int slen[NB];
    __shared__ int sidx[NB];
    int t = threadIdx.x;
    if (t < NB) slen[t] = lens[t];
    __syncthreads();
    if (t < NB) {
        int Li = slen[t];
        int r = 0;
        for (int j = 0; j < NB; j++) {
            int Lj = slen[j];
            if (Lj > Li || (Lj == Li && j < t)) r++;
        }
        sidx[r] = t;
    }
    __syncthreads();
    if (t < NB) { g_sort[t] = sidx[t]; g_dlen[t] = slen[sidx[t]] - 1; }
    __syncthreads();
    if (t == 0) {
        int s = 0;
        for (int b = 0; b < NB; b++) { g_cum[b] = s; s += slen[sidx[b]] - 1; }
        g_cum[NB] = s;
        g_Atot = s;
    }
    if (extras) {
        for (int i = t; i < NB * CL; i += blockDim.x) {
            int b = i / CL, j = i % CL;
            out_extra[i] = (float)caps[sidx[b] * CL + j];
        }
        if (t < NB) out_extra[NB*CL + t]      = (float)(slen[sidx[t]] - 1);
        if (t < NB) out_extra[NB*CL + NB + t] = (float)sidx[t];
    }
}

// ---------------- zero inactive output rows ----------------
__global__ void k_zero(float* __restrict__ out) {
    int b = blockIdx.x / NT, t = blockIdx.x % NT;
    if (t < g_dlen[b]) return;
    float4 z = make_float4(0.f, 0.f, 0.f, 0.f);
    float* row = out + ((size_t)b * NT + t) * VD;
    for (int i = threadIdx.x * 4; i < VD; i += 256 * 4)
        *(float4*)&row[i] = z;
}

// ---------------- packers: fp32 -> swizzled fp16, 16B vectorized ----------------
__device__ __forceinline__ void pack8_hl(const float v[8], char* bhi, char* blo, int r, int c8) {
    __align__(16) __half hi[8], lo[8];
#pragma unroll
    for (int j = 0; j < 8; j++) {
        hi[j] = __float2half_rn(v[j]);
        lo[j] = __float2half_rn(v[j] - __half2float(hi[j]));
    }
    uint32_t off = (uint32_t)r * 128 + c8 * 2;
    uint32_t sw = off ^ ((off >> 3) & 0x70);
    *(uint4*)(bhi + sw) = *(uint4*)hi;
    *(uint4*)(blo + sw) = *(uint4*)lo;
}
__device__ __forceinline__ void pack8_s(const float v[8], char* bf, int r, int c8) {
    __align__(16) __half h[8];
#pragma unroll
    for (int j = 0; j < 8; j++) h[j] = __float2half_rn(v[j]);
    uint32_t off = (uint32_t)r * 128 + c8 * 2;
    uint32_t sw = off ^ ((off >> 3) & 0x70);
    *(uint4*)(bf + sw) = *(uint4*)h;
}

__global__ void k_packB(const float* __restrict__ wfc) {
    int tile = blockIdx.x, kc = blockIdx.y;
    char* bf = (char*)(g_Bf + ((size_t)tile * KC + kc) * 8192);
    for (int u = threadIdx.x; u < 1024; u += 256) {
        int r = u >> 3, c8 = (u & 7) * 8;
        int n = tile * 128 + r;
        float v[8];
        if (n < VD) {
            float4 a = *(const float4*)&wfc[(size_t)n * HD + kc * 64 + c8];
            float4 b = *(const float4*)&wfc[(size_t)n * HD + kc * 64 + c8 + 4];
            v[0]=a.x; v[1]=a.y; v[2]=a.z; v[3]=a.w; v[4]=b.x; v[5]=b.y; v[6]=b.z; v[7]=b.w;
        } else {
#pragma unroll
            for (int j = 0; j < 8; j++) v[j] = 0.f;
        }
        pack8_s(v, bf, r, c8);
    }
}

__global__ void k_packW(const float* __restrict__ wih) {
    int tile = blockIdx.x, kc = blockIdx.y;
    char* bf = (char*)(g_Whi + ((size_t)tile * KC + kc) * 8192);
    for (int u = threadIdx.x; u < 1024; u += 256) {
        int r = u >> 3, c8 = (u & 7) * 8;
        int n = tile * 128 + r;
        float v[8];
        float4 a = *(const float4*)&wih[(size_t)n * ED + kc * 64 + c8];
        float4 b = *(const float4*)&wih[(size_t)n * ED + kc * 64 + c8 + 4];
        v[0]=a.x; v[1]=a.y; v[2]=a.z; v[3]=a.w; v[4]=b.x; v[5]=b.y; v[6]=b.z; v[7]=b.w;
        pack8_s(v, bf, r, c8);
    }
}

// gathered sorted embedding rows (t-major rows; after k_sort) — hi/lo (A exact)
__global__ void k_packE(const float* __restrict__ emb, const int* __restrict__ caps) {
    int tile = blockIdx.x, kc = blockIdx.y;
    __shared__ int tok[128];
    char* bhi = (char*)(g_Ehi + ((size_t)tile * KC + kc) * 8192);
    char* blo = (char*)(g_Elo + ((size_t)tile * KC + kc) * 8192);
    if (threadIdx.x < 128) {
        int r = threadIdx.x;
        int t = tile * 2 + (r >> 6), b = r & 63;
        tok[r] = caps[g_sort[b] * CL + t];
    }
    __syncthreads();
    for (int u = threadIdx.x; u < 1024; u += 256) {
        int r = u >> 3, c8 = (u & 7) * 8;
        float v[8];
        const float* src = emb + (size_t)tok[r] * ED + kc * 64 + c8;
        float4 a = *(const float4*)src;
        float4 b = *(const float4*)(src + 4);
        v[0]=a.x; v[1]=a.y; v[2]=a.z; v[3]=a.w; v[4]=b.x; v[5]=b.y; v[6]=b.z; v[7]=b.w;
        pack8_hl(v, bhi, blo, r, c8);
    }
}

// ---------------- init h0/c0: K-split partials + fused reduce ----------------
__global__ void k_init_part(const float* __restrict__ enc,
                            const float* __restrict__ wh, const float* __restrict__ wc) {
    __shared__ float As[32][65], Bs[32][65];
    __shared__ int arow[64];
    const float* Wsel = blockIdx.z ? wc : wh;
    int tid = threadIdx.x;
    if (tid < 64) arow[tid] = g_sort[tid];
    __syncthreads();
    int n0 = blockIdx.x * 64;
    int ks = blockIdx.y;
    int tx = tid & 15, ty = tid >> 4;
    int lr = tid >> 2, ls = tid & 3;
    float acc[4][4] = {};
    for (int k0 = ks * 256; k0 < ks * 256 + 256; k0 += 32) {
        const float4* ap = (const float4*)(enc + (size_t)arow[lr] * ENCD + k0);
        stash_tile(As, lr, ls, ap[ls], ap[ls + 4]);
        const float4* bp = (const float4*)(Wsel + (size_t)(n0 + lr) * ENCD + k0);
        stash_tile(Bs, lr, ls, bp[ls], bp[ls + 4]);
        __syncthreads();
        mm_inner(As, Bs, acc, tx, ty);
        __syncthreads();
    }
    float* outp = g_ip[blockIdx.z * 8 + ks];
#pragma unroll
    for (int i = 0; i < 4; i++) {
        int m = ty*4 + i;
#pragma unroll
        for (int j = 0; j < 4; j++)
            outp[m * HD + n0 + tx*4 + j] = acc[i][j];
    }
}

__global__ void k_init_red(const float* __restrict__ bh, const float* __restrict__ bc) {
    int idx = blockIdx.x * 256 + threadIdx.x;
    int z = idx >> 15, r = idx & 32767;
    int n = r & 511;
    float s = 0.f;
#pragma unroll
    for (int p = 0; p < 8; p++) s += g_ip[z * 8 + p][r];
    if (z == 0) g_hbuf[0][r] = s + bh[n];
    else        g_c[r] = s + bc[n];
}

// ---------------- shared mma.sync mainloop (128x128 tile, fp16, bulk-copy fed) ----------------
// AS: A split hi/lo (adds al*bh term). BS: B split hi/lo (adds ah*bl term).
// chunk = 16KB * (2 + AS + BS)
template<bool AS, bool BS>
__device__ __forceinline__ void mma_mainloop(uint32_t sb, int tid,
        const __half* Ahi, const __half* Alo,
        const __half* Bhi, const __half* Blo,
        int mtile, int ntile, bool act0, bool act1, float acc[2][8][4]) {
    const uint32_t CHUNK = 16384u * (2 + (AS ? 1 : 0) + (BS ? 1 : 0));
    const uint32_t OFF_AL = 16384u;                       // valid if AS
    const uint32_t OFF_B  = AS ? 32768u : 16384u;
    const uint32_t OFF_BL = OFF_B + 16384u;               // valid if BS
    int lane = tid & 31, warp = tid >> 5;
    int m0 = (warp & 3) * 32, n0w = (warp >> 2) * 64;
    int rl = lane & 7, q = lane >> 3;
    bool mact[2] = {act0, act1};
    uint32_t mb = sb + 2 * CHUNK;
    if (tid == 0) {
        asm volatile("mbarrier.init.shared.b64 [%0], 1;" :: "r"(mb) : "memory");
        asm volatile("mbarrier.init.shared.b64 [%0], 1;" :: "r"(mb + 8) : "memory");
    }
    __syncthreads();
    if (tid == 0) {
        asm volatile("mbarrier.arrive.expect_tx.shared.b64 _, [%0], %1;"
                     :: "r"(mb), "r"(CHUNK) : "memory");
        bulk16k(sb,          Ahi + ((size_t)mtile * KC) * 8192, mb);
        if (AS) bulk16k(sb + OFF_AL, Alo + ((size_t)mtile * KC) * 8192, mb);
        bulk16k(sb + OFF_B,  Bhi + ((size_t)ntile * KC) * 8192, mb);
        if (BS) bulk16k(sb + OFF_BL, Blo + ((size_t)ntile * KC) * 8192, mb);
    }
    for (int c = 0; c < KC; c++) {
        uint32_t st = sb + (uint32_t)(c & 1) * CHUNK;
        if (tid == 0 && c + 1 < KC) {
            uint32_t st2 = sb + (uint32_t)((c + 1) & 1) * CHUNK;
            uint32_t mb2 = mb + 8 * ((c + 1) & 1);
            asm volatile("mbarrier.arrive.expect_tx.shared.b64 _, [%0], %1;"
                         :: "r"(mb2), "r"(CHUNK) : "memory");
            bulk16k(st2,          Ahi + ((size_t)mtile * KC + c + 1) * 8192, mb2);
            if (AS) bulk16k(st2 + OFF_AL, Alo + ((size_t)mtile * KC + c + 1) * 8192, mb2);
            bulk16k(st2 + OFF_B,  Bhi + ((size_t)ntile * KC + c + 1) * 8192, mb2);
            if (BS) bulk16k(st2 + OFF_BL, Blo + ((size_t)ntile * KC + c + 1) * 8192, mb2);
        }
        mbar_wait(mb + 8 * (c & 1), (c >> 1) & 1);
        uint32_t stA = st, stAl = st + OFF_AL, stB = st + OFF_B, stBl = st + OFF_BL;
#pragma unroll
        for (int s = 0; s < 4; s++) {
            uint32_t bh[8][2], bl[8][2];
#pragma unroll
            for (int g = 0; g < 4; g++) {
                int row = n0w + g * 16 + ((q >> 1) << 3) + rl;
                int off = row * 128 + s * 32 + ((q & 1) << 4);
                int sw = off ^ ((off >> 3) & 0x70);
                uint32_t r0, r1, r2, r3;
                LDSM4(r0, r1, r2, r3, stB + sw);
                bh[g*2][0] = r0; bh[g*2][1] = r1; bh[g*2+1][0] = r2; bh[g*2+1][1] = r3;
                if (BS) {
                    LDSM4(r0, r1, r2, r3, stBl + sw);
                    bl[g*2][0] = r0; bl[g*2][1] = r1; bl[g*2+1][0] = r2; bl[g*2+1][1] = r3;
                }
            }
#pragma unroll
            for (int f = 0; f < 2; f++) {
                if (!mact[f]) continue;
                int row = m0 + f * 16 + rl + ((q & 1) << 3);
                int off = row * 128 + s * 32 + ((q >> 1) << 4);
                int sw = off ^ ((off >> 3) & 0x70);
                uint32_t ah[4], al[4];
                LDSM4(ah[0], ah[1], ah[2], ah[3], stA + sw);
                if (AS) LDSM4(al[0], al[1], al[2], al[3], stAl + sw);
#pragma unroll
                for (int nf = 0; nf < 8; nf++) {
                    MMA16816(acc[f][nf], ah, bh[nf]);
                    if (BS) MMA16816(acc[f][nf], ah, bl[nf]);
                    if (AS) MMA16816(acc[f][nf], al, bh[nf]);
                }
            }
        }
        __syncthreads();
    }
}

// ---------------- XW on mma.sync: g_XW = embs @ w_ih^T + b_ih (2-term: A exact) ----------------
__global__ void __launch_bounds__(256, 1)
k_xw_mma(const float* __restrict__ bih) {
    extern __shared__ char smem[];
    uint32_t sb = s2u(smem);
    int tid = threadIdx.x;
    int lane = tid & 31, warp = tid >> 5;
    int m0 = (warp & 3) * 32, n0w = (warp >> 2) * 64;
    int mtile = blockIdx.x % MT, ntile = blockIdx.x / MT;

    float acc[2][8][4];
#pragma unroll
    for (int f = 0; f < 2; f++)
#pragma unroll
        for (int nf = 0; nf < 8; nf++)
#pragma unroll
            for (int e = 0; e < 4; e++) acc[f][nf][e] = 0.f;

    mma_mainloop<true, false>(sb, tid, g_Ehi, g_Elo, g_Whi, (const __half*)0,
                              mtile, ntile, true, true, acc);

#pragma unroll
    for (int f = 0; f < 2; f++) {
        int rbase = mtile * 128 + m0 + f * 16 + (lane >> 2);
#pragma unroll
        for (int rr = 0; rr < 2; rr++) {
            int r = rbase + rr * 8;
            float* orow = g_XW + (size_t)r * GD;
#pragma unroll
            for (int nf = 0; nf < 8; nf++) {
                int n = ntile * 128 + n0w + nf * 8 + ((lane & 3) << 1);
                float2 bb = __ldg((const float2*)&bih[n]);
                float2 v;
                v.x = acc[f][nf][rr * 2 + 0] + bb.x;
                v.y = acc[f][nf][rr * 2 + 1] + bb.y;
                *(float2*)&orow[n] = v;
            }
        }
    }
}

// ---------------- persistent recurrence: 1 global barrier per step, fused pack ----------------
__device__ __forceinline__ void gsync(unsigned target) {
    __syncthreads();
    if (threadIdx.x == 0) {
        __threadfence();
        unsigned old = atomicAdd(&g_cnt, 1);
        if (old == RB - 1) {
            atomicExch(&g_cnt, 0);
            __threadfence();
            atomicAdd(&g_phase, 1);
        } else {
            while ((int)(*(volatile unsigned*)&g_phase - target) < 0) {}
        }
    }
    __syncthreads();
}

// block bi owns output columns j in [bi*4, bi*4+4) across ALL four gates.
__global__ void __launch_bounds__(256, 1) k_rnn(const float* __restrict__ whh,
                                                const float* __restrict__ bhh) {
    extern __shared__ float sm[];
    float* w_s = sm;                       // [k=512][16]  (idx = gate*4 + q)
    float* h_s = sm + 512 * 16;            // [b=64][516]
    float* s_g = sm + 512 * 16 + 64 * 516; // [b=64][16]
    int tid = threadIdx.x, bi = blockIdx.x;
    int j0 = bi * 4;
    for (int i = tid; i < 16 * 512; i += 256) {
        int idx = i >> 9, k = i & 511;
        int n = (idx >> 2) * 512 + j0 + (idx & 3);   // gate=(idx>>2), q=(idx&3)
        w_s[k * 16 + idx] = whh[(size_t)n * HD + k];
    }
    int gb = tid >> 2, gn = tid & 3;       // gemm: batch gb, gate gn (4 q's)
    int pb = gb, q = gn;                   // pointwise: batch pb, column q
    float c_reg = g_c[pb * HD + j0 + q];
    int dl = __ldg(&g_dlen[pb]);
    int cumb = __ldg(&g_cum[pb]);
    float4 b4 = *(const float4*)&bhh[gn * 512 + j0];
    unsigned base = *(volatile unsigned*)&g_phase;
    unsigned lp = 0;
    __syncthreads();
    for (int t = 0; t < NT; t++) {
        const float* hsrc = g_hbuf[t & 1];
        for (int idx = tid; idx < (NB * HD) / 4; idx += 256) {
            int lin = idx * 4;
            int b = lin >> 9, k = lin & 511;
            float4 hv = __ldcg((const float4*)&hsrc[b * HD + k]);
            *(float4*)&h_s[b * 516 + k] = hv;
        }
        __syncthreads();
        float a0 = 0.f, a1 = 0.f, a2 = 0.f, a3 = 0.f;
        const float* hrow = &h_s[gb * 516];
#pragma unroll 8
        for (int k = 0; k < 512; k++) {
            float h = hrow[k];
            float4 w = *(const float4*)&w_s[k * 16 + gn * 4];
            a0 += h * w.x; a1 += h * w.y; a2 += h * w.z; a3 += h * w.w;
        }
        float4 xv = __ldg((const float4*)&g_XW[((size_t)t * NB + gb) * GD + gn * 512 + j0]);
        *(float4*)&s_g[gb * 16 + gn * 4] =
            make_float4(a0 + xv.x + b4.x, a1 + xv.y + b4.y,
                        a2 + xv.z + b4.z, a3 + xv.w + b4.w);
        __syncthreads();
        float gi = s_g[pb * 16 + 0  + q];
        float gf = s_g[pb * 16 + 4  + q];
        float gg = s_g[pb * 16 + 8  + q];
        float go = s_g[pb * 16 + 12 + q];
        float si = 1.f / (1.f + expf(-gi));
        float sf = 1.f / (1.f + expf(-gf));
        float so = 1.f / (1.f + expf(-go));
        c_reg = sf * c_reg + si * tanhf(gg);
        float hv = so * tanhf(c_reg);
        __stcg(&g_hbuf[(t + 1) & 1][pb * HD + j0 + q], hv);
        if (t < dl) {   // fused pack into compacted fp16 A-tiles (hi only; FC is 1-term)
            int cr = cumb + t;
            int tile = cr >> 7, r = cr & 127;
            int j = j0 + q, kc = j >> 6, cc = j & 63;
            uint32_t off = (uint32_t)r * 128 + cc * 2;
            uint32_t sw = off ^ ((off >> 3) & 0x70);
            g_Af[((size_t)tile * KC + kc) * 8192 + (sw >> 1)] = __float2half_rn(hv);
        }
        gsync(base + (++lp));
    }
}

// ---------------- FC on mma.sync over compacted rows (1-term fp16) ----------------
__global__ void __launch_bounds__(256, 1)
k_fc_mma(const float* __restrict__ bfc, float* __restrict__ out) {
    extern __shared__ char smem[];
    __shared__ int cum_s[65];
    uint32_t sb = s2u(smem);
    int tid = threadIdx.x;
    int lane = tid & 31, warp = tid >> 5;
    int m0 = (warp & 3) * 32, n0w = (warp >> 2) * 64;
    int mtile = blockIdx.x % MT, ntile = blockIdx.x / MT;

    int Atot = __ldg(&g_Atot);
    if (mtile * 128 >= Atot) return;
    if (tid < 65) cum_s[tid] = g_cum[tid];

    bool act0 = (mtile * 128 + m0) < Atot;
    bool act1 = (mtile * 128 + m0 + 16) < Atot;

    float acc[2][8][4];
#pragma unroll
    for (int f = 0; f < 2; f++)
#pragma unroll
        for (int nf = 0; nf < 8; nf++)
#pragma unroll
            for (int e = 0; e < 4; e++) acc[f][nf][e] = 0.f;

    mma_mainloop<false, false>(sb, tid, g_Af, (const __half*)0, g_Bf, (const __half*)0,
                               mtile, ntile, act0, act1, acc);

#pragma unroll
    for (int f = 0; f < 2; f++) {
        int rbase = mtile * 128 + m0 + f * 16 + (lane >> 2);
#pragma unroll
        for (int rr = 0; rr < 2; rr++) {
            int r = rbase + rr * 8;
            if (r >= Atot) continue;
            int lo = 0, hi = 63;
            while (lo < hi) {                 // largest b with cum_s[b] <= r
                int mid = (lo + hi + 1) >> 1;
                if (cum_s[mid] <= r) lo = mid; else hi = mid - 1;
            }
            int b = lo, t = r - cum_s[lo];
            float* orow = out + ((size_t)b * NT + t) * VD;
#pragma unroll
            for (int nf = 0; nf < 8; nf++) {
                int n = ntile * 128 + n0w + nf * 8 + ((lane & 3) << 1);
                if (n < VD) {
                    float2 bb = __ldg((const float2*)&bfc[n]);
                    float2 v;
                    v.x = acc[f][nf][rr * 2 + 0] + bb.x;
                    v.y = acc[f][nf][rr * 2 + 1] + bb.y;
                    *(float2*)&orow[n] = v;
                }
            }
        }
    }
}

// ---------------- launch ----------------
extern "C" void kernel_launch(void* const* d_in, const int* in_sizes, int n_in,
                              void* d_out, int out_size) {
    const float* enc      = (const float*)d_in[0];
    const int*   caps     = (const int*)  d_in[1];
    const int*   clen     = (const int*)  d_in[2];
    const float* emb      = (const float*)d_in[3];
    const float* w_ih     = (const float*)d_in[4];
    const float* b_ih     = (const float*)d_in[5];
    const float* w_hh     = (const float*)d_in[6];
    const float* b_hh     = (const float*)d_in[7];
    const float* w_init_h = (const float*)d_in[8];
    const float* b_init_h = (const float*)d_in[9];
    const float* w_init_c = (const float*)d_in[10];
    const float* b_init_c = (const float*)d_in[11];
    const float* w_fc     = (const float*)d_in[12];
    const float* b_fc     = (const float*)d_in[13];
    float* out = (float*)d_out;

    const long long pred_elems = (long long)NB * NT * VD;
    int extras = ((long long)out_size > pred_elems) ? 1 : 0;

    const int rnn_smem = (512 * 16 + 64 * 516 + 64 * 16) * 4;   // 168960
    const int xw_smem  = 2 * 49152 + 128;    // AS chunk = 48KB
    const int fc_smem  = 2 * 32768 + 128;    // 1-term chunk = 32KB
    cudaFuncSetAttribute(k_rnn,    cudaFuncAttributeMaxDynamicSharedMemorySize, rnn_smem);
    cudaFuncSetAttribute(k_fc_mma, cudaFuncAttributeMaxDynamicSharedMemorySize, fc_smem);
    cudaFuncSetAttribute(k_xw_mma, cudaFuncAttributeMaxDynamicSharedMemorySize, xw_smem);

    k_sort<<<1, 256>>>(clen, caps, out + pred_elems, extras);
    k_zero<<<NB * NT, 256>>>(out);
    k_packB<<<dim3(NTB, KC), 256>>>(w_fc);
    k_packW<<<dim3(NTW, KC), 256>>>(w_ih);
    k_packE<<<dim3(MT, KC), 256>>>(emb, caps);
    k_init_part<<<dim3(HD / 64, 8, 2), 256>>>(enc, w_init_h, w_init_c);
    k_init_red<<<256, 256>>>(b_init_h, b_init_c);
    k_xw_mma<<<MT * NTW, 256, xw_smem>>>(b_ih);
    k_rnn<<<RB, 256, rnn_smem>>>(w_hh, b_hh);
    k_fc_mma<<<MT * NTB, 256, fc_smem>>>(b_fc, out);
}